// round 3
// baseline (speedup 1.0000x reference)
#include <cuda_runtime.h>
#include <cuda_bf16.h>
#include <cstdint>
#include <cstddef>

// ============================================================
// BiRealLinear: out[m,n] = scale[n] * sum_k sign(x[m,k])*sign(w[n,k])
// M=8192 (=4*2048), N=4096, K=4096
// Quantize signs -> bf16 (+/-1) + per-row mean|w| scale, then bf16 GEMM.
// GEMM has two compile-time paths:
//   - tcgen05 cg1 SS (only when the sm_103a arch-feature target is compiled)
//   - warp-level mma.sync.m16n8k16 bf16 fallback (plain sm_103 / any sm_90+)
// ============================================================

#define M_DIM 8192
#define N_DIM 4096
#define K_DIM 4096

#if defined(__CUDA_ARCH_FEAT_SM103_ALL) || defined(__CUDA_ARCH_FEAT_SM100_ALL)
#define HAS_TCGEN05 1
#else
#define HAS_TCGEN05 0
#endif

// -------- scratch (device globals: no allocation allowed) --------
__device__ __nv_bfloat16 g_xq[(size_t)M_DIM * K_DIM];   // 64 MB
__device__ __nv_bfloat16 g_wq[(size_t)N_DIM * K_DIM];   // 32 MB
__device__ float         g_scale[N_DIM];

// ---------------- common helpers ----------------
__device__ __forceinline__ uint32_t smem_u32(const void* p) {
    uint32_t a;
    asm("{ .reg .u64 t; cvta.to.shared.u64 t, %1; cvt.u32.u64 %0, t; }"
        : "=r"(a) : "l"(p));
    return a;
}

// SW128 swizzle (Swizzle<3,4,3>)
#define SMEM_SWIZZLE_128B(off) ((off) ^ (((off) >> 3) & 0x70))

// ---------------- quantize kernels ----------------
__global__ void quant_x_kernel(const float* __restrict__ x) {
    size_t i = (size_t)blockIdx.x * blockDim.x + threadIdx.x;  // float4 index
    float4 v = ((const float4*)x)[i];
    uint32_t lo = ((v.x > 0.f) ? 0x3F80u : 0xBF80u) | (((v.y > 0.f) ? 0x3F80u : 0xBF80u) << 16);
    uint32_t hi = ((v.z > 0.f) ? 0x3F80u : 0xBF80u) | (((v.w > 0.f) ? 0x3F80u : 0xBF80u) << 16);
    ((uint2*)g_xq)[i] = make_uint2(lo, hi);
}

__global__ void quant_w_kernel(const float* __restrict__ w) {
    size_t i = (size_t)blockIdx.x * blockDim.x + threadIdx.x;
    float4 v = ((const float4*)w)[i];
    uint32_t lo = ((v.x > 0.f) ? 0x3F80u : 0xBF80u) | (((v.y > 0.f) ? 0x3F80u : 0xBF80u) << 16);
    uint32_t hi = ((v.z > 0.f) ? 0x3F80u : 0xBF80u) | (((v.w > 0.f) ? 0x3F80u : 0xBF80u) << 16);
    ((uint2*)g_wq)[i] = make_uint2(lo, hi);
}

__global__ void wscale_kernel(const float* __restrict__ w) {
    int row = blockIdx.x;
    const float4* wr = (const float4*)(w + (size_t)row * K_DIM);
    float s = 0.f;
    for (int i = threadIdx.x; i < K_DIM / 4; i += 256) {
        float4 v = wr[i];
        s += fabsf(v.x) + fabsf(v.y) + fabsf(v.z) + fabsf(v.w);
    }
#pragma unroll
    for (int o = 16; o; o >>= 1) s += __shfl_xor_sync(0xFFFFFFFFu, s, o);
    __shared__ float sh[8];
    if ((threadIdx.x & 31) == 0) sh[threadIdx.x >> 5] = s;
    __syncthreads();
    if (threadIdx.x == 0) {
        float t = 0.f;
#pragma unroll
        for (int j = 0; j < 8; j++) t += sh[j];
        g_scale[row] = t * (1.0f / (float)K_DIM);
    }
}

// ---------------- GEMM common layout ----------------
// BM=128, BN=128, BK=64 (=128B rows, SW128). 256 threads. Double-buffered.
// SMEM map: [0] tmem ptr, [8],[16] mbars, [64..576) scales, tiles @1024.
#define SM_TMEM   0
#define SM_MBAR0  8
#define SM_MBAR1  16
#define SM_SCALE  64
#define SM_TILES  1024
#define TILE_BYTES 16384                // 128 rows * 128 B
#define BUF_STRIDE (2 * TILE_BYTES)     // A + B per buffer
#define GEMM_SMEM_REQ (100 * 1024)      // pad to cap occupancy at 2 CTAs/SM
#define N_CHUNKS (K_DIM / 64)           // 64

#if HAS_TCGEN05
// ---------------- tcgen05 helpers ----------------
__device__ __forceinline__ uint32_t elect_one() {
    uint32_t pred;
    asm volatile(
        "{\n\t.reg .pred p;\n\t"
        "elect.sync _|p, 0xFFFFFFFF;\n\t"
        "selp.b32 %0, 1, 0, p;\n\t}"
        : "=r"(pred));
    return pred;
}

#define MBARRIER_INIT(addr, cnt) \
    asm volatile("mbarrier.init.shared.b64 [%0], %1;" :: "r"(addr), "r"(cnt) : "memory")

#define MBARRIER_WAIT_PARITY(mbar_addr, phase_parity) do {                         \
    uint32_t _mbar = (uint32_t)(mbar_addr);                                        \
    uint32_t _parity = (uint32_t)(phase_parity);                                   \
    uint32_t _done;                                                                \
    asm volatile(                                                                  \
        "{\n\t.reg .pred p;\n\t"                                                   \
        "mbarrier.try_wait.parity.acquire.cta.shared::cta.b64 p, [%1], %2;\n\t"    \
        "selp.b32 %0, 1, 0, p;\n\t}"                                               \
        : "=r"(_done) : "r"(_mbar), "r"(_parity) : "memory");                      \
    if (!_done) {                                                                  \
        asm volatile(                                                              \
            "{\n\t.reg .pred P1;\n\t"                                              \
            "WAIT_LOOP_%=:\n\t"                                                    \
            "mbarrier.try_wait.parity.acquire.cta.shared::cta.b64 P1, [%0], %1, 0x989680;\n\t" \
            "@P1 bra.uni WAIT_DONE_%=;\n\t"                                        \
            "bra.uni WAIT_LOOP_%=;\n\t"                                            \
            "WAIT_DONE_%=:\n\t}"                                                   \
            :: "r"(_mbar), "r"(_parity) : "memory");                               \
    }                                                                              \
} while (0)

#define TCGEN05_ALLOC(smem_addr, nCols) \
    asm volatile("tcgen05.alloc.cta_group::1.sync.aligned.shared::cta.b32 [%0], %1;" \
                 :: "r"((uint32_t)(smem_addr)), "r"((uint32_t)(nCols)) : "memory")
#define TCGEN05_DEALLOC(tmem_addr, nCols) \
    asm volatile("tcgen05.dealloc.cta_group::1.sync.aligned.b32 %0, %1;" \
                 :: "r"(tmem_addr), "r"((uint32_t)(nCols)))
#define TCGEN05_RELINQUISH() \
    asm volatile("tcgen05.relinquish_alloc_permit.cta_group::1.sync.aligned;")
#define TCGEN05_COMMIT(mbar_addr) \
    asm volatile("tcgen05.commit.cta_group::1.mbarrier::arrive::one.shared::cluster.b64 [%0];" \
                 :: "r"((uint32_t)(mbar_addr)) : "memory")
#define TCGEN05_WAIT_LD() \
    asm volatile("tcgen05.wait::ld.sync.aligned;" ::: "memory")
#define TCGEN05_FENCE_BEFORE() \
    asm volatile("tcgen05.fence::before_thread_sync;" ::: "memory")
#define TCGEN05_FENCE_AFTER() \
    asm volatile("tcgen05.fence::after_thread_sync;" ::: "memory")
#define FENCE_PROXY_ASYNC_SHARED_CTA() \
    asm volatile("fence.proxy.async.shared::cta;" ::: "memory")

#define TCGEN05_LD_32X32B_X32(r, tmem_addr) \
    asm volatile( \
        "tcgen05.ld.sync.aligned.32x32b.x32.b32 " \
        "{%0, %1, %2, %3, %4, %5, %6, %7, " \
        " %8, %9, %10, %11, %12, %13, %14, %15, " \
        " %16, %17, %18, %19, %20, %21, %22, %23, " \
        " %24, %25, %26, %27, %28, %29, %30, %31}, [%32];" \
        : "=r"((r)[0]),  "=r"((r)[1]),  "=r"((r)[2]),  "=r"((r)[3]), \
          "=r"((r)[4]),  "=r"((r)[5]),  "=r"((r)[6]),  "=r"((r)[7]), \
          "=r"((r)[8]),  "=r"((r)[9]),  "=r"((r)[10]), "=r"((r)[11]), \
          "=r"((r)[12]), "=r"((r)[13]), "=r"((r)[14]), "=r"((r)[15]), \
          "=r"((r)[16]), "=r"((r)[17]), "=r"((r)[18]), "=r"((r)[19]), \
          "=r"((r)[20]), "=r"((r)[21]), "=r"((r)[22]), "=r"((r)[23]), \
          "=r"((r)[24]), "=r"((r)[25]), "=r"((r)[26]), "=r"((r)[27]), \
          "=r"((r)[28]), "=r"((r)[29]), "=r"((r)[30]), "=r"((r)[31]) \
        : "r"(tmem_addr))

// SW128 K-major SMEM descriptor: layout=2, version=1, SBO=64, LBO=1
static __device__ __forceinline__ uint64_t make_smem_desc(uint32_t addr) {
    const uint64_t base =
        (uint64_t(2) << 61) | (uint64_t(1) << 46) | (uint64_t(64) << 32) | (uint64_t(1) << 16);
    return base | ((uint64_t)(addr >> 4) & 0x3FFF);
}

// cg1 SS bf16 MMA, M=128, N=128, f32 accum
__device__ __forceinline__ void mma_f16_ss(uint32_t d_tmem, uint64_t a_desc, uint64_t b_desc,
                                           uint32_t idesc, bool acc) {
    uint32_t en = acc ? 1u : 0u;
    asm volatile(
        "{\n\t.reg .pred p;\n\t"
        "setp.ne.u32 p, %5, 0;\n\t"
        "tcgen05.mma.cta_group::1.kind::f16 [%0], %1, %2, %3, {%4, %4, %4, %4}, p;\n\t}"
        :: "r"(d_tmem), "l"(a_desc), "l"(b_desc), "r"(idesc), "r"(0u), "r"(en)
        : "memory");
}
// idesc: dtype=F32(1<<4), atype=BF16(1<<7), btype=BF16(1<<10), N/8<<17, M/16<<24
#define GEMM_IDESC 0x8200490u  // M=128, N=128

#else
// ---------------- mma.sync fallback helpers ----------------
__device__ __forceinline__ void ldsm_x4(uint32_t& r0, uint32_t& r1, uint32_t& r2, uint32_t& r3,
                                        uint32_t addr) {
    asm volatile("ldmatrix.sync.aligned.m8n8.x4.shared.b16 {%0,%1,%2,%3}, [%4];"
                 : "=r"(r0), "=r"(r1), "=r"(r2), "=r"(r3) : "r"(addr));
}

__device__ __forceinline__ void mma16816(float* c, const uint32_t* a, const uint32_t* b) {
    asm volatile(
        "mma.sync.aligned.m16n8k16.row.col.f32.bf16.bf16.f32 "
        "{%0,%1,%2,%3}, {%4,%5,%6,%7}, {%8,%9}, {%0,%1,%2,%3};"
        : "+f"(c[0]), "+f"(c[1]), "+f"(c[2]), "+f"(c[3])
        : "r"(a[0]), "r"(a[1]), "r"(a[2]), "r"(a[3]), "r"(b[0]), "r"(b[1]));
}
#endif

// ---------------- GEMM kernel (256 threads, shared layout both paths) ----------------
__global__ void __launch_bounds__(256)
gemm_kernel(float* __restrict__ out) {
    extern __shared__ char smem[];
    uint32_t smem_base = smem_u32(smem);
    const int tid = threadIdx.x;
    const int wid = tid >> 5;
    const int lid = tid & 31;
    const int m0 = blockIdx.y * 128;
    const int n0 = blockIdx.x * 128;

    // per-thread global->smem mapping: 32 row-groups x 8 segs of 16B; 4 iters cover 128 rows
    const int rbase = tid >> 3;            // 0..31
    const int seg   = tid & 7;             // 0..7
    const __nv_bfloat16* gA0 = g_xq + (size_t)(m0 + rbase) * K_DIM + seg * 8;
    const __nv_bfloat16* gB0 = g_wq + (size_t)(n0 + rbase) * K_DIM + seg * 8;

    if (tid < 128) ((float*)(smem + SM_SCALE))[tid] = g_scale[n0 + tid];

#if HAS_TCGEN05
    // ======================= tcgen05 path =======================
    if (wid == 0) TCGEN05_ALLOC(smem_base + SM_TMEM, 256);
    if (tid == 0) {
        MBARRIER_INIT(smem_base + SM_MBAR0, 1);
        MBARRIER_INIT(smem_base + SM_MBAR1, 1);
    }
    __syncthreads();
    uint32_t tmem_base;
    asm volatile("ld.shared.b32 %0, [%1];" : "=r"(tmem_base) : "r"(smem_base + SM_TMEM));
    if (wid == 0) TCGEN05_RELINQUISH();

    int ph0 = 0, ph1 = 0;

    for (int c = 0; c < N_CHUNKS; c++) {
        const int b = c & 1;
        const uint32_t mbar = smem_base + (b ? SM_MBAR1 : SM_MBAR0);
        const int k0 = c * 64;

        // stage global loads in registers (hide L2 latency above the mbar wait)
        uint4 va[4], vb[4];
#pragma unroll
        for (int i = 0; i < 4; i++) {
            va[i] = *(const uint4*)(gA0 + (size_t)i * 32 * K_DIM + k0);
            vb[i] = *(const uint4*)(gB0 + (size_t)i * 32 * K_DIM + k0);
        }

        // backpressure: buffer b's previous MMA (chunk c-2) must be done
        if (c >= 2) {
            if (b == 0) { MBARRIER_WAIT_PARITY(mbar, ph0); ph0 ^= 1; }
            else        { MBARRIER_WAIT_PARITY(mbar, ph1); ph1 ^= 1; }
        }

        char* At = smem + SM_TILES + b * BUF_STRIDE;
        char* Bt = At + TILE_BYTES;
#pragma unroll
        for (int i = 0; i < 4; i++) {
            uint32_t off = (uint32_t)((i * 32 + rbase) * 128 + seg * 16);
            uint32_t sw = SMEM_SWIZZLE_128B(off);
            *(uint4*)(At + sw) = va[i];
            *(uint4*)(Bt + sw) = vb[i];
        }
        FENCE_PROXY_ASYNC_SHARED_CTA();
        __syncthreads();

        if (wid == 0) {
            if (elect_one()) {
                uint64_t ad = make_smem_desc(smem_base + SM_TILES + b * BUF_STRIDE);
                uint64_t bd = make_smem_desc(smem_base + SM_TILES + b * BUF_STRIDE + TILE_BYTES);
#pragma unroll
                for (int ks = 0; ks < 4; ks++) {  // 4 x K=16 per 64-chunk; +2 = 32B
                    mma_f16_ss(tmem_base, ad + ks * 2, bd + ks * 2, GEMM_IDESC,
                               (c > 0) || (ks > 0));
                }
                TCGEN05_COMMIT(mbar);
            }
        }
    }

    // drain last two chunks
    MBARRIER_WAIT_PARITY(smem_base + SM_MBAR0, ph0);
    MBARRIER_WAIT_PARITY(smem_base + SM_MBAR1, ph1);
    TCGEN05_FENCE_AFTER();

    // epilogue: subpartition (wid&3) rows; warps 0-3 cols 0-63, warps 4-7 cols 64-127
    const int sub = wid & 3;
    const int colbase = (wid >> 2) * 64;
    const int row = m0 + sub * 32 + lid;
    float* orow = out + (size_t)row * N_DIM + n0;
    const float* ss = (const float*)(smem + SM_SCALE);
#pragma unroll
    for (int cc = 0; cc < 64; cc += 32) {
        const int c0 = colbase + cc;
        uint32_t dr[32];
        TCGEN05_LD_32X32B_X32(dr, tmem_base + c0);
        TCGEN05_WAIT_LD();
#pragma unroll
        for (int j = 0; j < 32; j += 4) {
            float4 v;
            v.x = __uint_as_float(dr[j + 0]) * ss[c0 + j + 0];
            v.y = __uint_as_float(dr[j + 1]) * ss[c0 + j + 1];
            v.z = __uint_as_float(dr[j + 2]) * ss[c0 + j + 2];
            v.w = __uint_as_float(dr[j + 3]) * ss[c0 + j + 3];
            *(float4*)(orow + c0 + j) = v;
        }
    }
    TCGEN05_FENCE_BEFORE();
    __syncthreads();
    if (wid == 0) TCGEN05_DEALLOC(tmem_base, 256);

#else
    // ======================= mma.sync fallback path =======================
    // 8 warps: warp tile 64(M) x 32(N). warp_mi = wid&1, warp_ni = wid>>1.
    const int base_m = (wid & 1) * 64;
    const int base_n = (wid >> 1) * 32;

    float acc[4][4][4];  // [mt][nt][reg]
#pragma unroll
    for (int mt = 0; mt < 4; mt++)
#pragma unroll
        for (int nt = 0; nt < 4; nt++)
#pragma unroll
            for (int r = 0; r < 4; r++) acc[mt][nt][r] = 0.f;

    __syncthreads();  // scales visible

    // prologue: load chunk 0 into buffer 0
    {
        char* At = smem + SM_TILES;
        char* Bt = At + TILE_BYTES;
#pragma unroll
        for (int i = 0; i < 4; i++) {
            uint4 a = *(const uint4*)(gA0 + (size_t)i * 32 * K_DIM);
            uint4 bv = *(const uint4*)(gB0 + (size_t)i * 32 * K_DIM);
            uint32_t off = (uint32_t)((i * 32 + rbase) * 128 + seg * 16);
            uint32_t sw = SMEM_SWIZZLE_128B(off);
            *(uint4*)(At + sw) = a;
            *(uint4*)(Bt + sw) = bv;
        }
    }
    __syncthreads();

    for (int c = 0; c < N_CHUNKS; c++) {
        const int b = c & 1;

        // prefetch next chunk into registers
        uint4 va[4], vb[4];
        if (c + 1 < N_CHUNKS) {
            const int kn = (c + 1) * 64;
#pragma unroll
            for (int i = 0; i < 4; i++) {
                va[i] = *(const uint4*)(gA0 + (size_t)i * 32 * K_DIM + kn);
                vb[i] = *(const uint4*)(gB0 + (size_t)i * 32 * K_DIM + kn);
            }
        }

        // compute on buffer b
        const uint32_t Abase = smem_base + SM_TILES + b * BUF_STRIDE;
        const uint32_t Bbase = Abase + TILE_BYTES;
#pragma unroll
        for (int ks = 0; ks < 4; ks++) {
            uint32_t af[4][4];
            uint32_t bf[4][2];
#pragma unroll
            for (int mt = 0; mt < 4; mt++) {
                uint32_t off = (uint32_t)((base_m + mt * 16 + (lid & 15)) * 128 +
                                          ks * 32 + (lid >> 4) * 16);
                ldsm_x4(af[mt][0], af[mt][1], af[mt][2], af[mt][3],
                        Abase + SMEM_SWIZZLE_128B(off));
            }
#pragma unroll
            for (int np = 0; np < 2; np++) {
                int grp = lid >> 3;  // 0..3
                uint32_t off = (uint32_t)((base_n + np * 16 + (grp >> 1) * 8 + (lid & 7)) * 128 +
                                          ks * 32 + (grp & 1) * 16);
                ldsm_x4(bf[np * 2][0], bf[np * 2][1], bf[np * 2 + 1][0], bf[np * 2 + 1][1],
                        Bbase + SMEM_SWIZZLE_128B(off));
            }
#pragma unroll
            for (int mt = 0; mt < 4; mt++)
#pragma unroll
                for (int nt = 0; nt < 4; nt++)
                    mma16816(acc[mt][nt], af[mt], bf[nt]);
        }

        __syncthreads();  // all warps done reading buffer b
        if (c + 1 < N_CHUNKS) {
            char* At = smem + SM_TILES + (b ^ 1) * BUF_STRIDE;
            char* Bt = At + TILE_BYTES;
#pragma unroll
            for (int i = 0; i < 4; i++) {
                uint32_t off = (uint32_t)((i * 32 + rbase) * 128 + seg * 16);
                uint32_t sw = SMEM_SWIZZLE_128B(off);
                *(uint4*)(At + sw) = va[i];
                *(uint4*)(Bt + sw) = vb[i];
            }
            __syncthreads();
        }
    }

    // epilogue with per-column scale
    const float* ss = (const float*)(smem + SM_SCALE);
    const int g = lid >> 2;
    const int cb = (lid & 3) * 2;
#pragma unroll
    for (int mt = 0; mt < 4; mt++) {
#pragma unroll
        for (int nt = 0; nt < 4; nt++) {
            const int col = base_n + nt * 8 + cb;    // local col in [0,128)
            const float s0 = ss[col], s1 = ss[col + 1];
            const int r0 = m0 + base_m + mt * 16 + g;
            float2 v0 = make_float2(acc[mt][nt][0] * s0, acc[mt][nt][1] * s1);
            float2 v1 = make_float2(acc[mt][nt][2] * s0, acc[mt][nt][3] * s1);
            *(float2*)(out + (size_t)r0 * N_DIM + n0 + col) = v0;
            *(float2*)(out + (size_t)(r0 + 8) * N_DIM + n0 + col) = v1;
        }
    }
#endif
}

// ---------------- launch ----------------
extern "C" void kernel_launch(void* const* d_in, const int* in_sizes, int n_in,
                              void* d_out, int out_size) {
    (void)in_sizes; (void)n_in; (void)out_size;
    const float* x = (const float*)d_in[0];
    const float* w = (const float*)d_in[1];
    float* out = (float*)d_out;

    // quantize + scales
    quant_x_kernel<<<(int)((M_DIM * (size_t)K_DIM / 4) / 256), 256>>>(x);
    quant_w_kernel<<<(int)((N_DIM * (size_t)K_DIM / 4) / 256), 256>>>(w);
    wscale_kernel<<<N_DIM, 256>>>(w);

    // GEMM (same config for both compiled paths)
    cudaFuncSetAttribute(gemm_kernel, cudaFuncAttributeMaxDynamicSharedMemorySize,
                         GEMM_SMEM_REQ);
    dim3 grid(N_DIM / 128, M_DIM / 128);  // (32, 64)
    gemm_kernel<<<grid, 256, GEMM_SMEM_REQ>>>(out);
}

// round 4
// speedup vs baseline: 2.1378x; 2.1378x over previous
#include <cuda_runtime.h>
#include <cuda_bf16.h>
#include <cstdint>
#include <cstddef>

// ============================================================
// BiRealLinear: out[m,n] = scale[n] * sum_k sign(x[m,k])*sign(w[n,k])
// M=8192, N=4096, K=4096
// Two GEMM kernels, each compiled to a real body in exactly one ptxas pass:
//   gemm_tc : tcgen05 cg1 SS path  (sm_103a feature pass only)
//   gemm_fb : mma.sync m16n8k16 path (non-'a' pass only)
// The driver loads one cubin; the other kernel is an empty stub there.
// Both use a 3-stage cp.async (LDGSTS) pipeline, BK=64, BM=BN=128.
// ============================================================

#define M_DIM 8192
#define N_DIM 4096
#define K_DIM 4096

#if defined(__CUDA_ARCH_FEAT_SM103_ALL) || defined(__CUDA_ARCH_FEAT_SM100_ALL)
#define HAS_TCGEN05 1
#else
#define HAS_TCGEN05 0
#endif

// -------- scratch (device globals: no allocation allowed) --------
__device__ __nv_bfloat16 g_xq[(size_t)M_DIM * K_DIM];   // 64 MB
__device__ __nv_bfloat16 g_wq[(size_t)N_DIM * K_DIM];   // 32 MB
__device__ float         g_scale[N_DIM];

// ---------------- common helpers ----------------
__device__ __forceinline__ uint32_t smem_u32(const void* p) {
    uint32_t a;
    asm("{ .reg .u64 t; cvta.to.shared.u64 t, %1; cvt.u32.u64 %0, t; }"
        : "=r"(a) : "l"(p));
    return a;
}

#define SMEM_SWIZZLE_128B(off) ((off) ^ (((off) >> 3) & 0x70))

#define CP_COMMIT() asm volatile("cp.async.commit_group;" ::: "memory")
#define CP_WAIT1()  asm volatile("cp.async.wait_group 1;" ::: "memory")
#define CP_WAIT0()  asm volatile("cp.async.wait_group 0;" ::: "memory")

// copy one BK=64 chunk (A 128x64, B 128x64 bf16) into a stage via cp.async.
// gA/gB pre-offset to (row rbase, col seg*8). 8 x 16B per thread.
__device__ __forceinline__ void cp_tile(uint32_t At, uint32_t Bt,
                                        const __nv_bfloat16* __restrict__ gA,
                                        const __nv_bfloat16* __restrict__ gB,
                                        int k0, int rbase, int seg) {
#pragma unroll
    for (int i = 0; i < 4; i++) {
        uint32_t off = (uint32_t)((i * 32 + rbase) * 128 + seg * 16);
        uint32_t sw = SMEM_SWIZZLE_128B(off);
        const void* srcA = (const void*)(gA + (size_t)i * 32 * K_DIM + k0);
        const void* srcB = (const void*)(gB + (size_t)i * 32 * K_DIM + k0);
        asm volatile("cp.async.cg.shared.global [%0], [%1], 16;"
                     :: "r"(At + sw), "l"(srcA) : "memory");
        asm volatile("cp.async.cg.shared.global [%0], [%1], 16;"
                     :: "r"(Bt + sw), "l"(srcB) : "memory");
    }
}

// ---------------- quantize kernels ----------------
__global__ void quant_x_kernel(const float* __restrict__ x) {
    size_t i = (size_t)blockIdx.x * blockDim.x + threadIdx.x;  // float4 index
    float4 v = ((const float4*)x)[i];
    uint32_t lo = ((v.x > 0.f) ? 0x3F80u : 0xBF80u) | (((v.y > 0.f) ? 0x3F80u : 0xBF80u) << 16);
    uint32_t hi = ((v.z > 0.f) ? 0x3F80u : 0xBF80u) | (((v.w > 0.f) ? 0x3F80u : 0xBF80u) << 16);
    ((uint2*)g_xq)[i] = make_uint2(lo, hi);
}

// fused: sign-pack w row + per-row mean|w| scale (one pass over w)
__global__ void quant_w_fused_kernel(const float* __restrict__ w) {
    const int row = blockIdx.x;
    const float4* wr = (const float4*)(w + (size_t)row * K_DIM);
    uint2* outw = (uint2*)(g_wq + (size_t)row * K_DIM);
    float s = 0.f;
#pragma unroll
    for (int j = 0; j < 4; j++) {
        int i = threadIdx.x + j * 256;
        float4 v = wr[i];
        s += fabsf(v.x) + fabsf(v.y) + fabsf(v.z) + fabsf(v.w);
        uint32_t lo = ((v.x > 0.f) ? 0x3F80u : 0xBF80u) | (((v.y > 0.f) ? 0x3F80u : 0xBF80u) << 16);
        uint32_t hi = ((v.z > 0.f) ? 0x3F80u : 0xBF80u) | (((v.w > 0.f) ? 0x3F80u : 0xBF80u) << 16);
        outw[i] = make_uint2(lo, hi);
    }
#pragma unroll
    for (int o = 16; o; o >>= 1) s += __shfl_xor_sync(0xFFFFFFFFu, s, o);
    __shared__ float sh[8];
    if ((threadIdx.x & 31) == 0) sh[threadIdx.x >> 5] = s;
    __syncthreads();
    if (threadIdx.x == 0) {
        float t = 0.f;
#pragma unroll
        for (int j = 0; j < 8; j++) t += sh[j];
        g_scale[row] = t * (1.0f / (float)K_DIM);
    }
}

// ---------------- GEMM shared layout ----------------
// BM=128, BN=128, BK=64 (128B rows, SW128). 256 threads. 3 cp.async stages.
// SMEM: [0] tmem ptr, [8/16/24] mbars, [64..576) scales, tiles @1024.
#define SM_TMEM   0
#define SM_MBAR   8
#define SM_SCALE  64
#define SM_TILES  1024
#define TILE_BYTES 16384                  // 128 rows * 128 B
#define STAGE_BYTES (2 * TILE_BYTES)      // A + B per stage
#define N_STAGES 3
#define GEMM_SMEM_REQ (SM_TILES + N_STAGES * STAGE_BYTES + 512)   // ~99.8 KB -> 2 CTA/SM
#define N_CHUNKS (K_DIM / 64)             // 64

#if HAS_TCGEN05
// ---------------- tcgen05 helpers ----------------
__device__ __forceinline__ uint32_t elect_one() {
    uint32_t pred;
    asm volatile(
        "{\n\t.reg .pred p;\n\t"
        "elect.sync _|p, 0xFFFFFFFF;\n\t"
        "selp.b32 %0, 1, 0, p;\n\t}"
        : "=r"(pred));
    return pred;
}

#define MBARRIER_INIT(addr, cnt) \
    asm volatile("mbarrier.init.shared.b64 [%0], %1;" :: "r"(addr), "r"(cnt) : "memory")

#define MBARRIER_WAIT_PARITY(mbar_addr, phase_parity) do {                         \
    uint32_t _mbar = (uint32_t)(mbar_addr);                                        \
    uint32_t _parity = (uint32_t)(phase_parity);                                   \
    uint32_t _done;                                                                \
    asm volatile(                                                                  \
        "{\n\t.reg .pred p;\n\t"                                                   \
        "mbarrier.try_wait.parity.acquire.cta.shared::cta.b64 p, [%1], %2;\n\t"    \
        "selp.b32 %0, 1, 0, p;\n\t}"                                               \
        : "=r"(_done) : "r"(_mbar), "r"(_parity) : "memory");                      \
    if (!_done) {                                                                  \
        asm volatile(                                                              \
            "{\n\t.reg .pred P1;\n\t"                                              \
            "WAIT_LOOP_%=:\n\t"                                                    \
            "mbarrier.try_wait.parity.acquire.cta.shared::cta.b64 P1, [%0], %1, 0x989680;\n\t" \
            "@P1 bra.uni WAIT_DONE_%=;\n\t"                                        \
            "bra.uni WAIT_LOOP_%=;\n\t"                                            \
            "WAIT_DONE_%=:\n\t}"                                                   \
            :: "r"(_mbar), "r"(_parity) : "memory");                               \
    }                                                                              \
} while (0)

#define TCGEN05_ALLOC(smem_addr, nCols) \
    asm volatile("tcgen05.alloc.cta_group::1.sync.aligned.shared::cta.b32 [%0], %1;" \
                 :: "r"((uint32_t)(smem_addr)), "r"((uint32_t)(nCols)) : "memory")
#define TCGEN05_DEALLOC(tmem_addr, nCols) \
    asm volatile("tcgen05.dealloc.cta_group::1.sync.aligned.b32 %0, %1;" \
                 :: "r"(tmem_addr), "r"((uint32_t)(nCols)))
#define TCGEN05_RELINQUISH() \
    asm volatile("tcgen05.relinquish_alloc_permit.cta_group::1.sync.aligned;")
#define TCGEN05_COMMIT(mbar_addr) \
    asm volatile("tcgen05.commit.cta_group::1.mbarrier::arrive::one.shared::cluster.b64 [%0];" \
                 :: "r"((uint32_t)(mbar_addr)) : "memory")
#define TCGEN05_WAIT_LD() \
    asm volatile("tcgen05.wait::ld.sync.aligned;" ::: "memory")
#define TCGEN05_FENCE_BEFORE() \
    asm volatile("tcgen05.fence::before_thread_sync;" ::: "memory")
#define TCGEN05_FENCE_AFTER() \
    asm volatile("tcgen05.fence::after_thread_sync;" ::: "memory")

#define TCGEN05_LD_32X32B_X32(r, tmem_addr) \
    asm volatile( \
        "tcgen05.ld.sync.aligned.32x32b.x32.b32 " \
        "{%0, %1, %2, %3, %4, %5, %6, %7, " \
        " %8, %9, %10, %11, %12, %13, %14, %15, " \
        " %16, %17, %18, %19, %20, %21, %22, %23, " \
        " %24, %25, %26, %27, %28, %29, %30, %31}, [%32];" \
        : "=r"((r)[0]),  "=r"((r)[1]),  "=r"((r)[2]),  "=r"((r)[3]), \
          "=r"((r)[4]),  "=r"((r)[5]),  "=r"((r)[6]),  "=r"((r)[7]), \
          "=r"((r)[8]),  "=r"((r)[9]),  "=r"((r)[10]), "=r"((r)[11]), \
          "=r"((r)[12]), "=r"((r)[13]), "=r"((r)[14]), "=r"((r)[15]), \
          "=r"((r)[16]), "=r"((r)[17]), "=r"((r)[18]), "=r"((r)[19]), \
          "=r"((r)[20]), "=r"((r)[21]), "=r"((r)[22]), "=r"((r)[23]), \
          "=r"((r)[24]), "=r"((r)[25]), "=r"((r)[26]), "=r"((r)[27]), \
          "=r"((r)[28]), "=r"((r)[29]), "=r"((r)[30]), "=r"((r)[31]) \
        : "r"(tmem_addr))

static __device__ __forceinline__ uint64_t make_smem_desc(uint32_t addr) {
    const uint64_t base =
        (uint64_t(2) << 61) | (uint64_t(1) << 46) | (uint64_t(64) << 32) | (uint64_t(1) << 16);
    return base | ((uint64_t)(addr >> 4) & 0x3FFF);
}

__device__ __forceinline__ void mma_f16_ss(uint32_t d_tmem, uint64_t a_desc, uint64_t b_desc,
                                           uint32_t idesc, bool acc) {
    uint32_t en = acc ? 1u : 0u;
    asm volatile(
        "{\n\t.reg .pred p;\n\t"
        "setp.ne.u32 p, %5, 0;\n\t"
        "tcgen05.mma.cta_group::1.kind::f16 [%0], %1, %2, %3, {%4, %4, %4, %4}, p;\n\t}"
        :: "r"(d_tmem), "l"(a_desc), "l"(b_desc), "r"(idesc), "r"(0u), "r"(en)
        : "memory");
}
#define GEMM_IDESC 0x8200490u  // f32 accum, bf16 x bf16, M=128, N=128
#endif  // HAS_TCGEN05

#if !HAS_TCGEN05
// ---------------- mma.sync helpers ----------------
__device__ __forceinline__ void ldsm_x4(uint32_t& r0, uint32_t& r1, uint32_t& r2, uint32_t& r3,
                                        uint32_t addr) {
    asm volatile("ldmatrix.sync.aligned.m8n8.x4.shared.b16 {%0,%1,%2,%3}, [%4];"
                 : "=r"(r0), "=r"(r1), "=r"(r2), "=r"(r3) : "r"(addr));
}

__device__ __forceinline__ void mma16816(float* c, const uint32_t* a, const uint32_t* b) {
    asm volatile(
        "mma.sync.aligned.m16n8k16.row.col.f32.bf16.bf16.f32 "
        "{%0,%1,%2,%3}, {%4,%5,%6,%7}, {%8,%9}, {%0,%1,%2,%3};"
        : "+f"(c[0]), "+f"(c[1]), "+f"(c[2]), "+f"(c[3])
        : "r"(a[0]), "r"(a[1]), "r"(a[2]), "r"(a[3]), "r"(b[0]), "r"(b[1]));
}
#endif

// ======================= gemm_tc: tcgen05 path =======================
__global__ void __launch_bounds__(256)
gemm_tc(float* __restrict__ out) {
#if HAS_TCGEN05
    extern __shared__ char smem[];
    uint32_t smem_base = smem_u32(smem);
    const int tid = threadIdx.x;
    const int wid = tid >> 5;
    const int lid = tid & 31;
    const int m0 = blockIdx.y * 128;
    const int n0 = blockIdx.x * 128;

    const int rbase = tid >> 3;            // 0..31
    const int seg   = tid & 7;             // 0..7
    const __nv_bfloat16* gA0 = g_xq + (size_t)(m0 + rbase) * K_DIM + seg * 8;
    const __nv_bfloat16* gB0 = g_wq + (size_t)(n0 + rbase) * K_DIM + seg * 8;

    if (tid < 128) ((float*)(smem + SM_SCALE))[tid] = g_scale[n0 + tid];

    if (wid == 0) TCGEN05_ALLOC(smem_base + SM_TMEM, 256);
    if (tid == 0) {
        MBARRIER_INIT(smem_base + SM_MBAR + 0, 1);
        MBARRIER_INIT(smem_base + SM_MBAR + 8, 1);
        MBARRIER_INIT(smem_base + SM_MBAR + 16, 1);
    }
    __syncthreads();
    uint32_t tmem_base;
    asm volatile("ld.shared.b32 %0, [%1];" : "=r"(tmem_base) : "r"(smem_base + SM_TMEM));
    if (wid == 0) TCGEN05_RELINQUISH();

    const uint32_t tiles = smem_base + SM_TILES;

    // prologue: chunks 0,1 into stages 0,1
    cp_tile(tiles + 0 * STAGE_BYTES, tiles + 0 * STAGE_BYTES + TILE_BYTES, gA0, gB0, 0, rbase, seg);
    CP_COMMIT();
    cp_tile(tiles + 1 * STAGE_BYTES, tiles + 1 * STAGE_BYTES + TILE_BYTES, gA0, gB0, 64, rbase, seg);
    CP_COMMIT();

    int ph0 = 0, ph1 = 0, ph2 = 0;
    int s = 0, s2 = 2;                    // compute stage, fill stage for chunk c+2

    for (int c = 0; c < N_CHUNKS; c++) {
        if (c < N_CHUNKS - 1) { CP_WAIT1(); } else { CP_WAIT0(); }
        __syncthreads();                  // stage s data visible CTA-wide

        if (wid == 0) {
            if (elect_one()) {
                const uint32_t sb = tiles + s * STAGE_BYTES;
                uint64_t ad = make_smem_desc(sb);
                uint64_t bd = make_smem_desc(sb + TILE_BYTES);
#pragma unroll
                for (int ks = 0; ks < 4; ks++) {
                    mma_f16_ss(tmem_base, ad + ks * 2, bd + ks * 2, GEMM_IDESC,
                               (c > 0) || (ks > 0));
                }
                TCGEN05_COMMIT(smem_base + SM_MBAR + s * 8);
            }
        }

        if (c + 2 < N_CHUNKS) {
            if (c + 2 >= N_STAGES) {     // stage s2 was used by chunk c-1: wait its MMA
                if (s2 == 0)      { MBARRIER_WAIT_PARITY(smem_base + SM_MBAR + 0, ph0);  ph0 ^= 1; }
                else if (s2 == 1) { MBARRIER_WAIT_PARITY(smem_base + SM_MBAR + 8, ph1);  ph1 ^= 1; }
                else              { MBARRIER_WAIT_PARITY(smem_base + SM_MBAR + 16, ph2); ph2 ^= 1; }
            }
            const uint32_t fb = tiles + s2 * STAGE_BYTES;
            cp_tile(fb, fb + TILE_BYTES, gA0, gB0, (c + 2) * 64, rbase, seg);
            CP_COMMIT();
        }
        s = (s == 2) ? 0 : s + 1;
        s2 = (s2 == 2) ? 0 : s2 + 1;
    }

    // drain: last chunk (63) committed to mbar[0]; in-order completion implies all done
    MBARRIER_WAIT_PARITY(smem_base + SM_MBAR + 0, ph0);
    TCGEN05_FENCE_AFTER();

    // epilogue: subpartition (wid&3) rows; warps 0-3 cols 0-63, warps 4-7 cols 64-127
    const int sub = wid & 3;
    const int colbase = (wid >> 2) * 64;
    const int row = m0 + sub * 32 + lid;
    float* orow = out + (size_t)row * N_DIM + n0;
    const float* ss = (const float*)(smem + SM_SCALE);
#pragma unroll
    for (int cc = 0; cc < 64; cc += 32) {
        const int c0 = colbase + cc;
        uint32_t dr[32];
        TCGEN05_LD_32X32B_X32(dr, tmem_base + c0);
        TCGEN05_WAIT_LD();
#pragma unroll
        for (int j = 0; j < 32; j += 4) {
            float4 v;
            v.x = __uint_as_float(dr[j + 0]) * ss[c0 + j + 0];
            v.y = __uint_as_float(dr[j + 1]) * ss[c0 + j + 1];
            v.z = __uint_as_float(dr[j + 2]) * ss[c0 + j + 2];
            v.w = __uint_as_float(dr[j + 3]) * ss[c0 + j + 3];
            *(float4*)(orow + c0 + j) = v;
        }
    }
    TCGEN05_FENCE_BEFORE();
    __syncthreads();
    if (wid == 0) TCGEN05_DEALLOC(tmem_base, 256);
#else
    (void)out;   // stub in non-'a' pass
#endif
}

// ======================= gemm_fb: mma.sync path =======================
__global__ void __launch_bounds__(256, 1)
gemm_fb(float* __restrict__ out) {
#if !HAS_TCGEN05
    extern __shared__ char smem[];
    uint32_t smem_base = smem_u32(smem);
    const int tid = threadIdx.x;
    const int wid = tid >> 5;
    const int lid = tid & 31;
    const int m0 = blockIdx.y * 128;
    const int n0 = blockIdx.x * 128;

    const int rbase = tid >> 3;
    const int seg   = tid & 7;
    const __nv_bfloat16* gA0 = g_xq + (size_t)(m0 + rbase) * K_DIM + seg * 8;
    const __nv_bfloat16* gB0 = g_wq + (size_t)(n0 + rbase) * K_DIM + seg * 8;

    if (tid < 128) ((float*)(smem + SM_SCALE))[tid] = g_scale[n0 + tid];

    // 8 warps: warp tile 64(M) x 32(N)
    const int base_m = (wid & 1) * 64;
    const int base_n = (wid >> 1) * 32;

    float acc[4][4][4];
#pragma unroll
    for (int mt = 0; mt < 4; mt++)
#pragma unroll
        for (int nt = 0; nt < 4; nt++)
#pragma unroll
            for (int r = 0; r < 4; r++) acc[mt][nt][r] = 0.f;

    const uint32_t tiles = smem_base + SM_TILES;

    // prologue: chunks 0,1
    cp_tile(tiles + 0 * STAGE_BYTES, tiles + 0 * STAGE_BYTES + TILE_BYTES, gA0, gB0, 0, rbase, seg);
    CP_COMMIT();
    cp_tile(tiles + 1 * STAGE_BYTES, tiles + 1 * STAGE_BYTES + TILE_BYTES, gA0, gB0, 64, rbase, seg);
    CP_COMMIT();

    int s = 0, s2 = 2;
    for (int c = 0; c < N_CHUNKS; c++) {
        if (c < N_CHUNKS - 1) { CP_WAIT1(); } else { CP_WAIT0(); }
        __syncthreads();      // stage s ready; stage s2 reads (iter c-1) finished

        if (c + 2 < N_CHUNKS) {
            const uint32_t fb = tiles + s2 * STAGE_BYTES;
            cp_tile(fb, fb + TILE_BYTES, gA0, gB0, (c + 2) * 64, rbase, seg);
            CP_COMMIT();
        }

        const uint32_t Abase = tiles + s * STAGE_BYTES;
        const uint32_t Bbase = Abase + TILE_BYTES;
#pragma unroll
        for (int ks = 0; ks < 4; ks++) {
            uint32_t af[4][4];
            uint32_t bf[4][2];
#pragma unroll
            for (int mt = 0; mt < 4; mt++) {
                uint32_t off = (uint32_t)((base_m + mt * 16 + (lid & 15)) * 128 +
                                          ks * 32 + (lid >> 4) * 16);
                ldsm_x4(af[mt][0], af[mt][1], af[mt][2], af[mt][3],
                        Abase + SMEM_SWIZZLE_128B(off));
            }
#pragma unroll
            for (int np = 0; np < 2; np++) {
                int grp = lid >> 3;
                uint32_t off = (uint32_t)((base_n + np * 16 + (grp >> 1) * 8 + (lid & 7)) * 128 +
                                          ks * 32 + (grp & 1) * 16);
                ldsm_x4(bf[np * 2][0], bf[np * 2][1], bf[np * 2 + 1][0], bf[np * 2 + 1][1],
                        Bbase + SMEM_SWIZZLE_128B(off));
            }
#pragma unroll
            for (int mt = 0; mt < 4; mt++)
#pragma unroll
                for (int nt = 0; nt < 4; nt++)
                    mma16816(acc[mt][nt], af[mt], bf[nt]);
        }
        s = (s == 2) ? 0 : s + 1;
        s2 = (s2 == 2) ? 0 : s2 + 1;
    }

    // epilogue with per-column scale
    const float* ss = (const float*)(smem + SM_SCALE);
    const int g = lid >> 2;
    const int cb = (lid & 3) * 2;
#pragma unroll
    for (int mt = 0; mt < 4; mt++) {
#pragma unroll
        for (int nt = 0; nt < 4; nt++) {
            const int col = base_n + nt * 8 + cb;
            const float s0 = ss[col], s1 = ss[col + 1];
            const int r0 = m0 + base_m + mt * 16 + g;
            float2 v0 = make_float2(acc[mt][nt][0] * s0, acc[mt][nt][1] * s1);
            float2 v1 = make_float2(acc[mt][nt][2] * s0, acc[mt][nt][3] * s1);
            *(float2*)(out + (size_t)r0 * N_DIM + n0 + col) = v0;
            *(float2*)(out + (size_t)(r0 + 8) * N_DIM + n0 + col) = v1;
        }
    }
#else
    (void)out;   // stub in 'a' pass
#endif
}

// ---------------- launch ----------------
extern "C" void kernel_launch(void* const* d_in, const int* in_sizes, int n_in,
                              void* d_out, int out_size) {
    (void)in_sizes; (void)n_in; (void)out_size;
    const float* x = (const float*)d_in[0];
    const float* w = (const float*)d_in[1];
    float* out = (float*)d_out;

    quant_x_kernel<<<(int)((M_DIM * (size_t)K_DIM / 4) / 256), 256>>>(x);
    quant_w_fused_kernel<<<N_DIM, 256>>>(w);

    cudaFuncSetAttribute(gemm_tc, cudaFuncAttributeMaxDynamicSharedMemorySize, GEMM_SMEM_REQ);
    cudaFuncSetAttribute(gemm_fb, cudaFuncAttributeMaxDynamicSharedMemorySize, GEMM_SMEM_REQ);
    dim3 grid(N_DIM / 128, M_DIM / 128);  // (32, 64)
    gemm_tc<<<grid, 256, GEMM_SMEM_REQ>>>(out);   // real body only in sm_103a cubin
    gemm_fb<<<grid, 256, GEMM_SMEM_REQ>>>(out);   // real body only in sm_103 cubin
}

// round 6
// speedup vs baseline: 3.3562x; 1.5699x over previous
#include <cuda_runtime.h>
#include <cuda_bf16.h>
#include <cstdint>
#include <cstddef>

// ============================================================
// BiRealLinear: out[m,n] = scale[n] * sum_k sign(x[m,k])*sign(w[n,k])
// M=8192, N=4096, K=4096
// Signs stored as e4m3 (+1 = 0x38, -1 = 0xB8): exact in fp8, exact fp32 accum.
// gemm_tc : tcgen05 cg1 SS kind::f8f6f4, BM=128 BN=256 BK=128,
//           4-stage cp.async pipeline.        (sm_103a feature pass only)
// gemm_fb : simple tiled FMA insurance path.  (non-'a' pass only; never runs
//           when the sm_103a cubin is loaded — proven by R4 profile)
// ============================================================

#define M_DIM 8192
#define N_DIM 4096
#define K_DIM 4096

#if defined(__CUDA_ARCH_FEAT_SM103_ALL) || defined(__CUDA_ARCH_FEAT_SM100_ALL)
#define HAS_TCGEN05 1
#else
#define HAS_TCGEN05 0
#endif

// -------- scratch (device globals: no allocation allowed) --------
__device__ uint8_t g_xq[(size_t)M_DIM * K_DIM];   // 32 MB e4m3 signs
__device__ uint8_t g_wq[(size_t)N_DIM * K_DIM];   // 16 MB e4m3 signs
__device__ float   g_scale[N_DIM];

// ---------------- common helpers ----------------
__device__ __forceinline__ uint32_t smem_u32(const void* p) {
    uint32_t a;
    asm("{ .reg .u64 t; cvta.to.shared.u64 t, %1; cvt.u32.u64 %0, t; }"
        : "=r"(a) : "l"(p));
    return a;
}

#define SMEM_SWIZZLE_128B(off) ((off) ^ (((off) >> 3) & 0x70))

#define CP_COMMIT() asm volatile("cp.async.commit_group;" ::: "memory")
#define CP_WAIT2()  asm volatile("cp.async.wait_group 2;" ::: "memory")
#define CP_WAIT1()  asm volatile("cp.async.wait_group 1;" ::: "memory")
#define CP_WAIT0()  asm volatile("cp.async.wait_group 0;" ::: "memory")

// e4m3 sign byte: +1.0 -> 0x38, -1.0 -> 0xB8
__device__ __forceinline__ uint32_t sgn8(float v) { return (v > 0.f) ? 0x38u : 0xB8u; }

// ---------------- quantize kernels ----------------
// x: 8 floats per thread -> 8 e4m3 bytes
__global__ void quant_x_kernel(const float* __restrict__ x) {
    size_t gid = (size_t)blockIdx.x * blockDim.x + threadIdx.x;
    const float4* xp = (const float4*)x;
    float4 a = xp[gid * 2];
    float4 b = xp[gid * 2 + 1];
    uint32_t lo = sgn8(a.x) | (sgn8(a.y) << 8) | (sgn8(a.z) << 16) | (sgn8(a.w) << 24);
    uint32_t hi = sgn8(b.x) | (sgn8(b.y) << 8) | (sgn8(b.z) << 16) | (sgn8(b.w) << 24);
    ((uint2*)g_xq)[gid] = make_uint2(lo, hi);
}

// fused: sign-pack w row (e4m3) + per-row mean|w| scale (one pass over w)
__global__ void quant_w_fused_kernel(const float* __restrict__ w) {
    const int row = blockIdx.x;
    const float4* wr = (const float4*)(w + (size_t)row * K_DIM);
    uint32_t* outw = (uint32_t*)(g_wq + (size_t)row * K_DIM);
    float s = 0.f;
#pragma unroll
    for (int j = 0; j < 4; j++) {
        int i = threadIdx.x + j * 256;
        float4 v = wr[i];
        s += fabsf(v.x) + fabsf(v.y) + fabsf(v.z) + fabsf(v.w);
        outw[i] = sgn8(v.x) | (sgn8(v.y) << 8) | (sgn8(v.z) << 16) | (sgn8(v.w) << 24);
    }
#pragma unroll
    for (int o = 16; o; o >>= 1) s += __shfl_xor_sync(0xFFFFFFFFu, s, o);
    __shared__ float sh[8];
    if ((threadIdx.x & 31) == 0) sh[threadIdx.x >> 5] = s;
    __syncthreads();
    if (threadIdx.x == 0) {
        float t = 0.f;
#pragma unroll
        for (int j = 0; j < 8; j++) t += sh[j];
        g_scale[row] = t * (1.0f / (float)K_DIM);
    }
}

// ---------------- GEMM (tc) layout ----------------
// BM=128, BN=256, BK=128 fp8 (128B rows, SW128 native). 256 threads.
// 4-stage cp.async pipeline, per-stage tcgen05 completion mbarriers.
#define BM 128
#define BN 256
#define BK 128
#define N_CHUNKS (K_DIM / BK)             // 32
#define A_TILE_BYTES (BM * 128)           // 16 KB
#define B_TILE_BYTES (BN * 128)           // 32 KB
#define STAGE_BYTES (A_TILE_BYTES + B_TILE_BYTES)  // 48 KB
#define N_STAGES 4
#define SM_TMEM   0
#define SM_MBAR   8                       // 4 mbarriers, 8B each
#define SM_SCALE  64                      // 256 floats
#define SM_TILES  2048                    // 1024-aligned
#define GEMM_SMEM_REQ (SM_TILES + N_STAGES * STAGE_BYTES)  // 198656 B
// idesc: f32 accum (1<<4), a=e4m3(0), b=e4m3(0), N>>3=32 (<<17), M>>4=8 (<<24)
#define GEMM_IDESC 0x8400010u

#if HAS_TCGEN05
// ---------------- tcgen05 helpers ----------------
__device__ __forceinline__ uint32_t elect_one() {
    uint32_t pred;
    asm volatile(
        "{\n\t.reg .pred p;\n\t"
        "elect.sync _|p, 0xFFFFFFFF;\n\t"
        "selp.b32 %0, 1, 0, p;\n\t}"
        : "=r"(pred));
    return pred;
}

#define MBARRIER_INIT(addr, cnt) \
    asm volatile("mbarrier.init.shared.b64 [%0], %1;" :: "r"(addr), "r"(cnt) : "memory")

#define MBARRIER_WAIT_PARITY(mbar_addr, phase_parity) do {                         \
    uint32_t _mbar = (uint32_t)(mbar_addr);                                        \
    uint32_t _parity = (uint32_t)(phase_parity);                                   \
    uint32_t _done;                                                                \
    asm volatile(                                                                  \
        "{\n\t.reg .pred p;\n\t"                                                   \
        "mbarrier.try_wait.parity.acquire.cta.shared::cta.b64 p, [%1], %2;\n\t"    \
        "selp.b32 %0, 1, 0, p;\n\t}"                                               \
        : "=r"(_done) : "r"(_mbar), "r"(_parity) : "memory");                      \
    if (!_done) {                                                                  \
        asm volatile(                                                              \
            "{\n\t.reg .pred P1;\n\t"                                              \
            "WAIT_LOOP_%=:\n\t"                                                    \
            "mbarrier.try_wait.parity.acquire.cta.shared::cta.b64 P1, [%0], %1, 0x989680;\n\t" \
            "@P1 bra.uni WAIT_DONE_%=;\n\t"                                        \
            "bra.uni WAIT_LOOP_%=;\n\t"                                            \
            "WAIT_DONE_%=:\n\t}"                                                   \
            :: "r"(_mbar), "r"(_parity) : "memory");                               \
    }                                                                              \
} while (0)

#define TCGEN05_ALLOC(smem_addr, nCols) \
    asm volatile("tcgen05.alloc.cta_group::1.sync.aligned.shared::cta.b32 [%0], %1;" \
                 :: "r"((uint32_t)(smem_addr)), "r"((uint32_t)(nCols)) : "memory")
#define TCGEN05_DEALLOC(tmem_addr, nCols) \
    asm volatile("tcgen05.dealloc.cta_group::1.sync.aligned.b32 %0, %1;" \
                 :: "r"(tmem_addr), "r"((uint32_t)(nCols)))
#define TCGEN05_RELINQUISH() \
    asm volatile("tcgen05.relinquish_alloc_permit.cta_group::1.sync.aligned;")
#define TCGEN05_COMMIT(mbar_addr) \
    asm volatile("tcgen05.commit.cta_group::1.mbarrier::arrive::one.shared::cluster.b64 [%0];" \
                 :: "r"((uint32_t)(mbar_addr)) : "memory")
#define TCGEN05_WAIT_LD() \
    asm volatile("tcgen05.wait::ld.sync.aligned;" ::: "memory")
#define TCGEN05_FENCE_BEFORE() \
    asm volatile("tcgen05.fence::before_thread_sync;" ::: "memory")
#define TCGEN05_FENCE_AFTER() \
    asm volatile("tcgen05.fence::after_thread_sync;" ::: "memory")

#define TCGEN05_LD_32X32B_X32(r, tmem_addr) \
    asm volatile( \
        "tcgen05.ld.sync.aligned.32x32b.x32.b32 " \
        "{%0, %1, %2, %3, %4, %5, %6, %7, " \
        " %8, %9, %10, %11, %12, %13, %14, %15, " \
        " %16, %17, %18, %19, %20, %21, %22, %23, " \
        " %24, %25, %26, %27, %28, %29, %30, %31}, [%32];" \
        : "=r"((r)[0]),  "=r"((r)[1]),  "=r"((r)[2]),  "=r"((r)[3]), \
          "=r"((r)[4]),  "=r"((r)[5]),  "=r"((r)[6]),  "=r"((r)[7]), \
          "=r"((r)[8]),  "=r"((r)[9]),  "=r"((r)[10]), "=r"((r)[11]), \
          "=r"((r)[12]), "=r"((r)[13]), "=r"((r)[14]), "=r"((r)[15]), \
          "=r"((r)[16]), "=r"((r)[17]), "=r"((r)[18]), "=r"((r)[19]), \
          "=r"((r)[20]), "=r"((r)[21]), "=r"((r)[22]), "=r"((r)[23]), \
          "=r"((r)[24]), "=r"((r)[25]), "=r"((r)[26]), "=r"((r)[27]), \
          "=r"((r)[28]), "=r"((r)[29]), "=r"((r)[30]), "=r"((r)[31]) \
        : "r"(tmem_addr))

static __device__ __forceinline__ uint64_t make_smem_desc(uint32_t addr) {
    const uint64_t base =
        (uint64_t(2) << 61) | (uint64_t(1) << 46) | (uint64_t(64) << 32) | (uint64_t(1) << 16);
    return base | ((uint64_t)(addr >> 4) & 0x3FFF);
}

__device__ __forceinline__ void mma_f8_ss(uint32_t d_tmem, uint64_t a_desc, uint64_t b_desc,
                                          uint32_t idesc, bool acc) {
    uint32_t en = acc ? 1u : 0u;
    asm volatile(
        "{\n\t.reg .pred p;\n\t"
        "setp.ne.u32 p, %5, 0;\n\t"
        "tcgen05.mma.cta_group::1.kind::f8f6f4 [%0], %1, %2, %3, {%4, %4, %4, %4}, p;\n\t}"
        :: "r"(d_tmem), "l"(a_desc), "l"(b_desc), "r"(idesc), "r"(0u), "r"(en)
        : "memory");
}
#endif  // HAS_TCGEN05

// ======================= gemm_tc: tcgen05 fp8 path =======================
__global__ void __launch_bounds__(256)
gemm_tc(float* __restrict__ out) {
#if HAS_TCGEN05
    extern __shared__ char smem[];
    uint32_t smem_base = smem_u32(smem);
    const int tid = threadIdx.x;
    const int wid = tid >> 5;
    const int lid = tid & 31;
    const int m0 = blockIdx.y * BM;
    const int n0 = blockIdx.x * BN;

    // copy mapping: row-group rbase (0..31), 16B seg (0..7)
    const int rbase = tid >> 3;
    const int seg   = tid & 7;
    const uint8_t* gA = g_xq + (size_t)(m0 + rbase) * K_DIM + seg * 16;
    const uint8_t* gB = g_wq + (size_t)(n0 + rbase) * K_DIM + seg * 16;

    // scales (256 floats)
    ((float*)(smem + SM_SCALE))[tid] = g_scale[n0 + tid];

    if (wid == 0) TCGEN05_ALLOC(smem_base + SM_TMEM, 256);
    if (tid == 0) {
#pragma unroll
        for (int i = 0; i < N_STAGES; i++) MBARRIER_INIT(smem_base + SM_MBAR + i * 8, 1);
    }
    __syncthreads();
    uint32_t tmem_base;
    asm volatile("ld.shared.b32 %0, [%1];" : "=r"(tmem_base) : "r"(smem_base + SM_TMEM));
    if (wid == 0) TCGEN05_RELINQUISH();

    const uint32_t tiles = smem_base + SM_TILES;

    // fill one stage: A 128 rows (4 iters) + B 256 rows (8 iters)
    auto fill_stage = [&](int stage, int chunk) {
        const uint32_t At = tiles + stage * STAGE_BYTES;
        const uint32_t Bt = At + A_TILE_BYTES;
        const int kb = chunk * BK;
#pragma unroll
        for (int i = 0; i < 4; i++) {
            uint32_t sw = SMEM_SWIZZLE_128B((uint32_t)((i * 32 + rbase) * 128 + seg * 16));
            const void* src = (const void*)(gA + (size_t)i * 32 * K_DIM + kb);
            asm volatile("cp.async.cg.shared.global [%0], [%1], 16;"
                         :: "r"(At + sw), "l"(src) : "memory");
        }
#pragma unroll
        for (int i = 0; i < 8; i++) {
            uint32_t sw = SMEM_SWIZZLE_128B((uint32_t)((i * 32 + rbase) * 128 + seg * 16));
            const void* src = (const void*)(gB + (size_t)i * 32 * K_DIM + kb);
            asm volatile("cp.async.cg.shared.global [%0], [%1], 16;"
                         :: "r"(Bt + sw), "l"(src) : "memory");
        }
        CP_COMMIT();
    };

    // prologue: chunks 0..2 into stages 0..2
    fill_stage(0, 0);
    fill_stage(1, 1);
    fill_stage(2, 2);

    int ph0 = 0, ph1 = 0, ph2 = 0, ph3 = 0;

    for (int c = 0; c < N_CHUNKS; c++) {
        const int s = c & 3;
        // chunk c's copy must be done: keep <= min(2, remaining) groups in flight
        const int rem = N_CHUNKS - 1 - c;
        if (rem >= 2)      { CP_WAIT2(); }
        else if (rem == 1) { CP_WAIT1(); }
        else               { CP_WAIT0(); }
        __syncthreads();

        if (wid == 0) {
            if (elect_one()) {
                const uint32_t sb = tiles + s * STAGE_BYTES;
                uint64_t ad = make_smem_desc(sb);
                uint64_t bd = make_smem_desc(sb + A_TILE_BYTES);
#pragma unroll
                for (int ks = 0; ks < 4; ks++) {   // 4 x K=32 fp8 = BK=128; +2 units = 32B
                    mma_f8_ss(tmem_base, ad + ks * 2, bd + ks * 2, GEMM_IDESC,
                              (c > 0) || (ks > 0));
                }
                TCGEN05_COMMIT(smem_base + SM_MBAR + s * 8);
            }
        }

        if (c + 3 < N_CHUNKS) {
            const int sf = (c + 3) & 3;            // stage to refill (used by chunk c-1)
            if (c >= 1) {                          // wait chunk c-1's MMA completion
                if (sf == 0)      { MBARRIER_WAIT_PARITY(smem_base + SM_MBAR + 0,  ph0); ph0 ^= 1; }
                else if (sf == 1) { MBARRIER_WAIT_PARITY(smem_base + SM_MBAR + 8,  ph1); ph1 ^= 1; }
                else if (sf == 2) { MBARRIER_WAIT_PARITY(smem_base + SM_MBAR + 16, ph2); ph2 ^= 1; }
                else              { MBARRIER_WAIT_PARITY(smem_base + SM_MBAR + 24, ph3); ph3 ^= 1; }
            }
            fill_stage(sf, c + 3);
        }
    }

    // drain: last chunk (31) committed to mbar[3]; in-order completion => all done
    MBARRIER_WAIT_PARITY(smem_base + SM_MBAR + 24, ph3);
    TCGEN05_FENCE_AFTER();

    // epilogue: warp w -> rows (w&3)*32+lid, col half (w>>2)*128 of N=256
    const int sub = wid & 3;
    const int colhalf = (wid >> 2) * 128;
    const int row = m0 + sub * 32 + lid;
    float* orow = out + (size_t)row * N_DIM + n0;
    const float* ss = (const float*)(smem + SM_SCALE);
#pragma unroll
    for (int cc = 0; cc < 128; cc += 32) {
        const int c0 = colhalf + cc;
        uint32_t dr[32];
        TCGEN05_LD_32X32B_X32(dr, tmem_base + c0);
        TCGEN05_WAIT_LD();
#pragma unroll
        for (int j = 0; j < 32; j += 4) {
            float4 v;
            v.x = __uint_as_float(dr[j + 0]) * ss[c0 + j + 0];
            v.y = __uint_as_float(dr[j + 1]) * ss[c0 + j + 1];
            v.z = __uint_as_float(dr[j + 2]) * ss[c0 + j + 2];
            v.w = __uint_as_float(dr[j + 3]) * ss[c0 + j + 3];
            *(float4*)(orow + c0 + j) = v;
        }
    }
    TCGEN05_FENCE_BEFORE();
    __syncthreads();
    if (wid == 0) TCGEN05_DEALLOC(tmem_base, 256);
#else
    (void)out;   // stub in non-'a' pass
#endif
}

// ======================= gemm_fb: insurance path (slow, correct) =======================
// Tiled FMA over e4m3 sign bytes. 64x64 tile per block, 256 threads, 4x4 per thread.
__global__ void __launch_bounds__(256)
gemm_fb(float* __restrict__ out) {
#if !HAS_TCGEN05
    __shared__ uint8_t As[64][64];
    __shared__ uint8_t Bs[64][64];
    const int tid = threadIdx.x;
    const int tx = tid & 15, ty = tid >> 4;
    const int n0 = blockIdx.x * 64, m0 = blockIdx.y * 64;
    const int lrow = tid >> 2;            // 0..63
    const int lcol = (tid & 3) * 16;      // 16B segment

    float acc[4][4];
#pragma unroll
    for (int i = 0; i < 4; i++)
#pragma unroll
        for (int j = 0; j < 4; j++) acc[i][j] = 0.f;

    for (int kb = 0; kb < K_DIM; kb += 64) {
        *(uint4*)&As[lrow][lcol] =
            *(const uint4*)(g_xq + (size_t)(m0 + lrow) * K_DIM + kb + lcol);
        *(uint4*)&Bs[lrow][lcol] =
            *(const uint4*)(g_wq + (size_t)(n0 + lrow) * K_DIM + kb + lcol);
        __syncthreads();
#pragma unroll 8
        for (int k = 0; k < 64; k++) {
            float a[4], b[4];
#pragma unroll
            for (int i = 0; i < 4; i++) a[i] = (As[ty * 4 + i][k] & 0x80) ? -1.f : 1.f;
#pragma unroll
            for (int j = 0; j < 4; j++) b[j] = (Bs[tx * 4 + j][k] & 0x80) ? -1.f : 1.f;
#pragma unroll
            for (int i = 0; i < 4; i++)
#pragma unroll
                for (int j = 0; j < 4; j++) acc[i][j] += a[i] * b[j];
        }
        __syncthreads();
    }
#pragma unroll
    for (int i = 0; i < 4; i++)
#pragma unroll
        for (int j = 0; j < 4; j++) {
            const int col = n0 + tx * 4 + j;
            out[(size_t)(m0 + ty * 4 + i) * N_DIM + col] = acc[i][j] * g_scale[col];
        }
#else
    (void)out;   // stub in 'a' pass
#endif
}

// ---------------- launch ----------------
extern "C" void kernel_launch(void* const* d_in, const int* in_sizes, int n_in,
                              void* d_out, int out_size) {
    (void)in_sizes; (void)n_in; (void)out_size;
    const float* x = (const float*)d_in[0];
    const float* w = (const float*)d_in[1];
    float* out = (float*)d_out;

    quant_x_kernel<<<(int)((M_DIM * (size_t)K_DIM / 8) / 256), 256>>>(x);
    quant_w_fused_kernel<<<N_DIM, 256>>>(w);

    cudaFuncSetAttribute(gemm_tc, cudaFuncAttributeMaxDynamicSharedMemorySize, GEMM_SMEM_REQ);
    dim3 grid_tc(N_DIM / BN, M_DIM / BM);   // (16, 64)
    gemm_tc<<<grid_tc, 256, GEMM_SMEM_REQ>>>(out);   // real body only in sm_103a cubin

    dim3 grid_fb(N_DIM / 64, M_DIM / 64);   // (64, 128)
    gemm_fb<<<grid_fb, 256>>>(out);                  // real body only in sm_103 cubin
}

// round 7
// speedup vs baseline: 3.3735x; 1.0052x over previous
#include <cuda_runtime.h>
#include <cuda_bf16.h>
#include <cstdint>
#include <cstddef>

// ============================================================
// BiRealLinear: out[m,n] = scale[n] * sum_k sign(x[m,k])*sign(w[n,k])
// M=8192, N=4096, K=4096
// Signs as e4m3 (+1=0x38, -1=0xB8): exact fp8 products, exact fp32 accum.
// gemm_tc : tcgen05 cg1 SS kind::f8f6f4, BM=256 (2x M=128 MMA, 512-col TMEM),
//           BN=256, BK=128, 3-stage cp.async pipeline. (sm_103a pass only)
// gemm_fb : tiled FMA insurance path.                  (non-'a' pass only)
// Host picks the real kernel via cudaFuncGetAttributes (stub <= 16 regs).
// ============================================================

#define M_DIM 8192
#define N_DIM 4096
#define K_DIM 4096

#if defined(__CUDA_ARCH_FEAT_SM103_ALL) || defined(__CUDA_ARCH_FEAT_SM100_ALL)
#define HAS_TCGEN05 1
#else
#define HAS_TCGEN05 0
#endif

// -------- scratch (device globals: no allocation allowed) --------
__device__ uint8_t g_xq[(size_t)M_DIM * K_DIM];   // 32 MB e4m3 signs
__device__ uint8_t g_wq[(size_t)N_DIM * K_DIM];   // 16 MB e4m3 signs
__device__ float   g_scale[N_DIM];

// ---------------- common helpers ----------------
__device__ __forceinline__ uint32_t smem_u32(const void* p) {
    uint32_t a;
    asm("{ .reg .u64 t; cvta.to.shared.u64 t, %1; cvt.u32.u64 %0, t; }"
        : "=r"(a) : "l"(p));
    return a;
}

#define SMEM_SWIZZLE_128B(off) ((off) ^ (((off) >> 3) & 0x70))

#define CP_COMMIT() asm volatile("cp.async.commit_group;" ::: "memory")
#define CP_WAIT1()  asm volatile("cp.async.wait_group 1;" ::: "memory")
#define CP_WAIT0()  asm volatile("cp.async.wait_group 0;" ::: "memory")

// e4m3 sign byte: +1.0 -> 0x38, -1.0 -> 0xB8
__device__ __forceinline__ uint32_t sgn8(float v) { return (v > 0.f) ? 0x38u : 0xB8u; }

// ---------------- quantize kernels ----------------
__global__ void quant_x_kernel(const float* __restrict__ x) {
    size_t gid = (size_t)blockIdx.x * blockDim.x + threadIdx.x;
    const float4* xp = (const float4*)x;
    float4 a = xp[gid * 2];
    float4 b = xp[gid * 2 + 1];
    uint32_t lo = sgn8(a.x) | (sgn8(a.y) << 8) | (sgn8(a.z) << 16) | (sgn8(a.w) << 24);
    uint32_t hi = sgn8(b.x) | (sgn8(b.y) << 8) | (sgn8(b.z) << 16) | (sgn8(b.w) << 24);
    ((uint2*)g_xq)[gid] = make_uint2(lo, hi);
}

__global__ void quant_w_fused_kernel(const float* __restrict__ w) {
    const int row = blockIdx.x;
    const float4* wr = (const float4*)(w + (size_t)row * K_DIM);
    uint32_t* outw = (uint32_t*)(g_wq + (size_t)row * K_DIM);
    float s = 0.f;
#pragma unroll
    for (int j = 0; j < 4; j++) {
        int i = threadIdx.x + j * 256;
        float4 v = wr[i];
        s += fabsf(v.x) + fabsf(v.y) + fabsf(v.z) + fabsf(v.w);
        outw[i] = sgn8(v.x) | (sgn8(v.y) << 8) | (sgn8(v.z) << 16) | (sgn8(v.w) << 24);
    }
#pragma unroll
    for (int o = 16; o; o >>= 1) s += __shfl_xor_sync(0xFFFFFFFFu, s, o);
    __shared__ float sh[8];
    if ((threadIdx.x & 31) == 0) sh[threadIdx.x >> 5] = s;
    __syncthreads();
    if (threadIdx.x == 0) {
        float t = 0.f;
#pragma unroll
        for (int j = 0; j < 8; j++) t += sh[j];
        g_scale[row] = t * (1.0f / (float)K_DIM);
    }
}

// ---------------- GEMM (tc) layout ----------------
// BM=256, BN=256, BK=128 fp8 (128B rows, SW128 native). 256 threads.
// 3-stage cp.async pipeline; TMEM: D0 cols 0-255 (rows 0-127), D1 cols 256-511.
#define BM 256
#define BN 256
#define BK 128
#define N_CHUNKS (K_DIM / BK)             // 32
#define A_TILE_BYTES (BM * 128)           // 32 KB
#define B_TILE_BYTES (BN * 128)           // 32 KB
#define STAGE_BYTES (A_TILE_BYTES + B_TILE_BYTES)  // 64 KB
#define N_STAGES 3
#define SM_TMEM   0
#define SM_MBAR   8                       // 3 mbarriers, 8B each
#define SM_SCALE  64                      // 256 floats
#define SM_TILES  2048                    // 1024-aligned
#define GEMM_SMEM_REQ (SM_TILES + N_STAGES * STAGE_BYTES)  // 198656 B (~194 KB)
// idesc: f32 accum (1<<4), a=e4m3(0), b=e4m3(0), N>>3=32 (<<17), M>>4=8 (<<24)
#define GEMM_IDESC 0x8400010u

#if HAS_TCGEN05
// ---------------- tcgen05 helpers ----------------
__device__ __forceinline__ uint32_t elect_one() {
    uint32_t pred;
    asm volatile(
        "{\n\t.reg .pred p;\n\t"
        "elect.sync _|p, 0xFFFFFFFF;\n\t"
        "selp.b32 %0, 1, 0, p;\n\t}"
        : "=r"(pred));
    return pred;
}

#define MBARRIER_INIT(addr, cnt) \
    asm volatile("mbarrier.init.shared.b64 [%0], %1;" :: "r"(addr), "r"(cnt) : "memory")

#define MBARRIER_WAIT_PARITY(mbar_addr, phase_parity) do {                         \
    uint32_t _mbar = (uint32_t)(mbar_addr);                                        \
    uint32_t _parity = (uint32_t)(phase_parity);                                   \
    uint32_t _done;                                                                \
    asm volatile(                                                                  \
        "{\n\t.reg .pred p;\n\t"                                                   \
        "mbarrier.try_wait.parity.acquire.cta.shared::cta.b64 p, [%1], %2;\n\t"    \
        "selp.b32 %0, 1, 0, p;\n\t}"                                               \
        : "=r"(_done) : "r"(_mbar), "r"(_parity) : "memory");                      \
    if (!_done) {                                                                  \
        asm volatile(                                                              \
            "{\n\t.reg .pred P1;\n\t"                                              \
            "WAIT_LOOP_%=:\n\t"                                                    \
            "mbarrier.try_wait.parity.acquire.cta.shared::cta.b64 P1, [%0], %1, 0x989680;\n\t" \
            "@P1 bra.uni WAIT_DONE_%=;\n\t"                                        \
            "bra.uni WAIT_LOOP_%=;\n\t"                                            \
            "WAIT_DONE_%=:\n\t}"                                                   \
            :: "r"(_mbar), "r"(_parity) : "memory");                               \
    }                                                                              \
} while (0)

#define TCGEN05_ALLOC(smem_addr, nCols) \
    asm volatile("tcgen05.alloc.cta_group::1.sync.aligned.shared::cta.b32 [%0], %1;" \
                 :: "r"((uint32_t)(smem_addr)), "r"((uint32_t)(nCols)) : "memory")
#define TCGEN05_DEALLOC(tmem_addr, nCols) \
    asm volatile("tcgen05.dealloc.cta_group::1.sync.aligned.b32 %0, %1;" \
                 :: "r"(tmem_addr), "r"((uint32_t)(nCols)))
#define TCGEN05_RELINQUISH() \
    asm volatile("tcgen05.relinquish_alloc_permit.cta_group::1.sync.aligned;")
#define TCGEN05_COMMIT(mbar_addr) \
    asm volatile("tcgen05.commit.cta_group::1.mbarrier::arrive::one.shared::cluster.b64 [%0];" \
                 :: "r"((uint32_t)(mbar_addr)) : "memory")
#define TCGEN05_WAIT_LD() \
    asm volatile("tcgen05.wait::ld.sync.aligned;" ::: "memory")
#define TCGEN05_FENCE_BEFORE() \
    asm volatile("tcgen05.fence::before_thread_sync;" ::: "memory")
#define TCGEN05_FENCE_AFTER() \
    asm volatile("tcgen05.fence::after_thread_sync;" ::: "memory")

#define TCGEN05_LD_32X32B_X32(r, tmem_addr) \
    asm volatile( \
        "tcgen05.ld.sync.aligned.32x32b.x32.b32 " \
        "{%0, %1, %2, %3, %4, %5, %6, %7, " \
        " %8, %9, %10, %11, %12, %13, %14, %15, " \
        " %16, %17, %18, %19, %20, %21, %22, %23, " \
        " %24, %25, %26, %27, %28, %29, %30, %31}, [%32];" \
        : "=r"((r)[0]),  "=r"((r)[1]),  "=r"((r)[2]),  "=r"((r)[3]), \
          "=r"((r)[4]),  "=r"((r)[5]),  "=r"((r)[6]),  "=r"((r)[7]), \
          "=r"((r)[8]),  "=r"((r)[9]),  "=r"((r)[10]), "=r"((r)[11]), \
          "=r"((r)[12]), "=r"((r)[13]), "=r"((r)[14]), "=r"((r)[15]), \
          "=r"((r)[16]), "=r"((r)[17]), "=r"((r)[18]), "=r"((r)[19]), \
          "=r"((r)[20]), "=r"((r)[21]), "=r"((r)[22]), "=r"((r)[23]), \
          "=r"((r)[24]), "=r"((r)[25]), "=r"((r)[26]), "=r"((r)[27]), \
          "=r"((r)[28]), "=r"((r)[29]), "=r"((r)[30]), "=r"((r)[31]) \
        : "r"(tmem_addr))

static __device__ __forceinline__ uint64_t make_smem_desc(uint32_t addr) {
    const uint64_t base =
        (uint64_t(2) << 61) | (uint64_t(1) << 46) | (uint64_t(64) << 32) | (uint64_t(1) << 16);
    return base | ((uint64_t)(addr >> 4) & 0x3FFF);
}

__device__ __forceinline__ void mma_f8_ss(uint32_t d_tmem, uint64_t a_desc, uint64_t b_desc,
                                          uint32_t idesc, bool acc) {
    uint32_t en = acc ? 1u : 0u;
    asm volatile(
        "{\n\t.reg .pred p;\n\t"
        "setp.ne.u32 p, %5, 0;\n\t"
        "tcgen05.mma.cta_group::1.kind::f8f6f4 [%0], %1, %2, %3, {%4, %4, %4, %4}, p;\n\t}"
        :: "r"(d_tmem), "l"(a_desc), "l"(b_desc), "r"(idesc), "r"(0u), "r"(en)
        : "memory");
}
#endif  // HAS_TCGEN05

// ======================= gemm_tc: tcgen05 fp8 path, BM=256 =======================
__global__ void __launch_bounds__(256)
gemm_tc(float* __restrict__ out) {
#if HAS_TCGEN05
    extern __shared__ char smem[];
    uint32_t smem_base = smem_u32(smem);
    const int tid = threadIdx.x;
    const int wid = tid >> 5;
    const int lid = tid & 31;
    const int m0 = blockIdx.y * BM;
    const int n0 = blockIdx.x * BN;

    // copy mapping: row-group rbase (0..31), 16B seg (0..7)
    const int rbase = tid >> 3;
    const int seg   = tid & 7;
    const uint8_t* gA = g_xq + (size_t)(m0 + rbase) * K_DIM + seg * 16;
    const uint8_t* gB = g_wq + (size_t)(n0 + rbase) * K_DIM + seg * 16;

    ((float*)(smem + SM_SCALE))[tid] = g_scale[n0 + tid];

    if (wid == 0) TCGEN05_ALLOC(smem_base + SM_TMEM, 512);
    if (tid == 0) {
#pragma unroll
        for (int i = 0; i < N_STAGES; i++) MBARRIER_INIT(smem_base + SM_MBAR + i * 8, 1);
    }
    __syncthreads();
    uint32_t tmem_base;
    asm volatile("ld.shared.b32 %0, [%1];" : "=r"(tmem_base) : "r"(smem_base + SM_TMEM));
    if (wid == 0) TCGEN05_RELINQUISH();

    const uint32_t tiles = smem_base + SM_TILES;

    // fill one stage: A 256 rows (8 iters) + B 256 rows (8 iters), 16B each
    auto fill_stage = [&](int stage, int chunk) {
        const uint32_t At = tiles + stage * STAGE_BYTES;
        const uint32_t Bt = At + A_TILE_BYTES;
        const int kb = chunk * BK;
#pragma unroll
        for (int i = 0; i < 8; i++) {
            uint32_t sw = SMEM_SWIZZLE_128B((uint32_t)((i * 32 + rbase) * 128 + seg * 16));
            const void* srcA = (const void*)(gA + (size_t)i * 32 * K_DIM + kb);
            const void* srcB = (const void*)(gB + (size_t)i * 32 * K_DIM + kb);
            asm volatile("cp.async.cg.shared.global [%0], [%1], 16;"
                         :: "r"(At + sw), "l"(srcA) : "memory");
            asm volatile("cp.async.cg.shared.global [%0], [%1], 16;"
                         :: "r"(Bt + sw), "l"(srcB) : "memory");
        }
        CP_COMMIT();
    };

    // prologue: chunks 0,1 into stages 0,1
    fill_stage(0, 0);
    fill_stage(1, 1);

    int ph0 = 0, ph1 = 0, ph2 = 0;

    for (int c = 0; c < N_CHUNKS; c++) {
        const int s = c % 3;
        if (c < N_CHUNKS - 1) { CP_WAIT1(); } else { CP_WAIT0(); }
        __syncthreads();                  // stage s data visible CTA-wide

        if (wid == 0) {
            if (elect_one()) {
                const uint32_t sb = tiles + s * STAGE_BYTES;
                uint64_t ad0 = make_smem_desc(sb);                 // A rows 0-127
                uint64_t ad1 = ad0 + 1024;                         // A rows 128-255 (+16KB)
                uint64_t bd  = make_smem_desc(sb + A_TILE_BYTES);
#pragma unroll
                for (int ks = 0; ks < 4; ks++) {   // 4 x K=32 fp8 = BK=128
                    const bool acc = (c > 0) || (ks > 0);
                    mma_f8_ss(tmem_base,       ad0 + ks * 2, bd + ks * 2, GEMM_IDESC, acc);
                    mma_f8_ss(tmem_base + 256, ad1 + ks * 2, bd + ks * 2, GEMM_IDESC, acc);
                }
                TCGEN05_COMMIT(smem_base + SM_MBAR + s * 8);
            }
        }

        if (c + 2 < N_CHUNKS) {
            const int sf = (c + 2) % 3;            // stage used by chunk c-1
            if (c >= 1) {                          // wait chunk c-1's MMA completion
                if (sf == 0)      { MBARRIER_WAIT_PARITY(smem_base + SM_MBAR + 0,  ph0); ph0 ^= 1; }
                else if (sf == 1) { MBARRIER_WAIT_PARITY(smem_base + SM_MBAR + 8,  ph1); ph1 ^= 1; }
                else              { MBARRIER_WAIT_PARITY(smem_base + SM_MBAR + 16, ph2); ph2 ^= 1; }
            }
            fill_stage(sf, c + 2);
        }
    }

    // drain: last chunk (31) committed to mbar[31%3=1]; in-order => all done
    MBARRIER_WAIT_PARITY(smem_base + SM_MBAR + 8, ph1);
    TCGEN05_FENCE_AFTER();

    // epilogue:
    //   warps 0-3: D0 (cols 0-255)  rows m0 + (wid&3)*32 + lid
    //   warps 4-7: D1 (cols 256-511) rows m0 + 128 + (wid&3)*32 + lid
    const int half = wid >> 2;             // 0 or 1
    const int sub  = wid & 3;
    const int row = m0 + half * 128 + sub * 32 + lid;
    const uint32_t dbase = tmem_base + half * 256;
    float* orow = out + (size_t)row * N_DIM + n0;
    const float* ss = (const float*)(smem + SM_SCALE);
#pragma unroll
    for (int c0 = 0; c0 < 256; c0 += 32) {
        uint32_t dr[32];
        TCGEN05_LD_32X32B_X32(dr, dbase + c0);
        TCGEN05_WAIT_LD();
#pragma unroll
        for (int j = 0; j < 32; j += 4) {
            float4 v;
            v.x = __uint_as_float(dr[j + 0]) * ss[c0 + j + 0];
            v.y = __uint_as_float(dr[j + 1]) * ss[c0 + j + 1];
            v.z = __uint_as_float(dr[j + 2]) * ss[c0 + j + 2];
            v.w = __uint_as_float(dr[j + 3]) * ss[c0 + j + 3];
            *(float4*)(orow + c0 + j) = v;
        }
    }
    TCGEN05_FENCE_BEFORE();
    __syncthreads();
    if (wid == 0) TCGEN05_DEALLOC(tmem_base, 512);
#else
    (void)out;   // stub in non-'a' pass
#endif
}

// ======================= gemm_fb: insurance path (slow, correct) =======================
__global__ void __launch_bounds__(256)
gemm_fb(float* __restrict__ out) {
#if !HAS_TCGEN05
    __shared__ uint8_t As[64][64];
    __shared__ uint8_t Bs[64][64];
    const int tid = threadIdx.x;
    const int tx = tid & 15, ty = tid >> 4;
    const int n0 = blockIdx.x * 64, m0 = blockIdx.y * 64;
    const int lrow = tid >> 2;
    const int lcol = (tid & 3) * 16;

    float acc[4][4];
#pragma unroll
    for (int i = 0; i < 4; i++)
#pragma unroll
        for (int j = 0; j < 4; j++) acc[i][j] = 0.f;

    for (int kb = 0; kb < K_DIM; kb += 64) {
        *(uint4*)&As[lrow][lcol] =
            *(const uint4*)(g_xq + (size_t)(m0 + lrow) * K_DIM + kb + lcol);
        *(uint4*)&Bs[lrow][lcol] =
            *(const uint4*)(g_wq + (size_t)(n0 + lrow) * K_DIM + kb + lcol);
        __syncthreads();
#pragma unroll 8
        for (int k = 0; k < 64; k++) {
            float a[4], b[4];
#pragma unroll
            for (int i = 0; i < 4; i++) a[i] = (As[ty * 4 + i][k] & 0x80) ? -1.f : 1.f;
#pragma unroll
            for (int j = 0; j < 4; j++) b[j] = (Bs[tx * 4 + j][k] & 0x80) ? -1.f : 1.f;
#pragma unroll
            for (int i = 0; i < 4; i++)
#pragma unroll
                for (int j = 0; j < 4; j++) acc[i][j] += a[i] * b[j];
        }
        __syncthreads();
    }
#pragma unroll
    for (int i = 0; i < 4; i++)
#pragma unroll
        for (int j = 0; j < 4; j++) {
            const int col = n0 + tx * 4 + j;
            out[(size_t)(m0 + ty * 4 + i) * N_DIM + col] = acc[i][j] * g_scale[col];
        }
#else
    (void)out;   // stub in 'a' pass
#endif
}

// ---------------- launch ----------------
extern "C" void kernel_launch(void* const* d_in, const int* in_sizes, int n_in,
                              void* d_out, int out_size) {
    (void)in_sizes; (void)n_in; (void)out_size;
    const float* x = (const float*)d_in[0];
    const float* w = (const float*)d_in[1];
    float* out = (float*)d_out;

    quant_x_kernel<<<(int)((M_DIM * (size_t)K_DIM / 8) / 256), 256>>>(x);
    quant_w_fused_kernel<<<N_DIM, 256>>>(w);

    // Launch only the kernel whose body is real in the loaded cubin.
    // Stubs compile to <= 16 regs (measured); real bodies use >= 40.
    cudaFuncAttributes fa_tc{}, fa_fb{};
    cudaFuncGetAttributes(&fa_tc, gemm_tc);
    cudaFuncGetAttributes(&fa_fb, gemm_fb);

    if (fa_tc.numRegs > 24) {
        cudaFuncSetAttribute(gemm_tc, cudaFuncAttributeMaxDynamicSharedMemorySize,
                             GEMM_SMEM_REQ);
        dim3 grid_tc(N_DIM / BN, M_DIM / BM);   // (16, 32)
        gemm_tc<<<grid_tc, 256, GEMM_SMEM_REQ>>>(out);
    } else {
        dim3 grid_fb(N_DIM / 64, M_DIM / 64);   // (64, 128)
        gemm_fb<<<grid_fb, 256>>>(out);
        (void)fa_fb;
    }
}

// round 8
// speedup vs baseline: 3.5420x; 1.0499x over previous
#include <cuda_runtime.h>
#include <cuda_bf16.h>
#include <cstdint>
#include <cstddef>

// ============================================================
// BiRealLinear: out[m,n] = scale[n] * sum_k sign(x[m,k])*sign(w[n,k])
// M=8192, N=4096, K=4096
// Signs as e4m3 (+1=0x38, -1=0xB8): exact fp8 products, exact fp32 accum.
// gemm_tc : tcgen05 cg1 SS kind::f8f6f4, BM=256 (2x M=128), BN=256, BK=128.
//           288 threads: warp0 = MMA issuer, warps1-8 = cp.async producers.
//           mbarrier-paced 3-stage pipeline (no __syncthreads in mainloop).
// gemm_fb : tiled FMA insurance path (non-'a' pass only).
// Host picks the real kernel via cudaFuncGetAttributes (stub <= 16 regs).
// ============================================================

#define M_DIM 8192
#define N_DIM 4096
#define K_DIM 4096

#if defined(__CUDA_ARCH_FEAT_SM103_ALL) || defined(__CUDA_ARCH_FEAT_SM100_ALL)
#define HAS_TCGEN05 1
#else
#define HAS_TCGEN05 0
#endif

// -------- scratch (device globals: no allocation allowed) --------
__device__ uint8_t g_xq[(size_t)M_DIM * K_DIM];   // 32 MB e4m3 signs
__device__ uint8_t g_wq[(size_t)N_DIM * K_DIM];   // 16 MB e4m3 signs
__device__ float   g_scale[N_DIM];

// ---------------- common helpers ----------------
__device__ __forceinline__ uint32_t smem_u32(const void* p) {
    uint32_t a;
    asm("{ .reg .u64 t; cvta.to.shared.u64 t, %1; cvt.u32.u64 %0, t; }"
        : "=r"(a) : "l"(p));
    return a;
}

#define SMEM_SWIZZLE_128B(off) ((off) ^ (((off) >> 3) & 0x70))

// e4m3 sign byte: +1.0 -> 0x38, -1.0 -> 0xB8
__device__ __forceinline__ uint32_t sgn8(float v) { return (v > 0.f) ? 0x38u : 0xB8u; }

// ---------------- quantize kernels ----------------
__global__ void quant_x_kernel(const float* __restrict__ x) {
    size_t gid = (size_t)blockIdx.x * blockDim.x + threadIdx.x;
    const float4* xp = (const float4*)x;
    float4 a = xp[gid * 2];
    float4 b = xp[gid * 2 + 1];
    uint32_t lo = sgn8(a.x) | (sgn8(a.y) << 8) | (sgn8(a.z) << 16) | (sgn8(a.w) << 24);
    uint32_t hi = sgn8(b.x) | (sgn8(b.y) << 8) | (sgn8(b.z) << 16) | (sgn8(b.w) << 24);
    ((uint2*)g_xq)[gid] = make_uint2(lo, hi);
}

__global__ void quant_w_fused_kernel(const float* __restrict__ w) {
    const int row = blockIdx.x;
    const float4* wr = (const float4*)(w + (size_t)row * K_DIM);
    uint32_t* outw = (uint32_t*)(g_wq + (size_t)row * K_DIM);
    float s = 0.f;
#pragma unroll
    for (int j = 0; j < 4; j++) {
        int i = threadIdx.x + j * 256;
        float4 v = wr[i];
        s += fabsf(v.x) + fabsf(v.y) + fabsf(v.z) + fabsf(v.w);
        outw[i] = sgn8(v.x) | (sgn8(v.y) << 8) | (sgn8(v.z) << 16) | (sgn8(v.w) << 24);
    }
#pragma unroll
    for (int o = 16; o; o >>= 1) s += __shfl_xor_sync(0xFFFFFFFFu, s, o);
    __shared__ float sh[8];
    if ((threadIdx.x & 31) == 0) sh[threadIdx.x >> 5] = s;
    __syncthreads();
    if (threadIdx.x == 0) {
        float t = 0.f;
#pragma unroll
        for (int j = 0; j < 8; j++) t += sh[j];
        g_scale[row] = t * (1.0f / (float)K_DIM);
    }
}

// ---------------- GEMM (tc) layout ----------------
#define BM 256
#define BN 256
#define BK 128
#define N_CHUNKS (K_DIM / BK)             // 32
#define A_TILE_BYTES (BM * 128)           // 32 KB
#define B_TILE_BYTES (BN * 128)           // 32 KB
#define STAGE_BYTES (A_TILE_BYTES + B_TILE_BYTES)  // 64 KB
#define N_STAGES 3
#define SM_TMEM   0
#define SM_FULL   8                       // 3 full-mbarriers (count 256)
#define SM_DONE   32                      // 3 done-mbarriers (count 1)
#define SM_SCALE  64                      // 256 floats
#define SM_TILES  2048
#define GEMM_SMEM_REQ (SM_TILES + N_STAGES * STAGE_BYTES)  // 198656 B
#define TC_THREADS 288
// idesc: f32 accum (1<<4), a=e4m3(0), b=e4m3(0), N>>3=32 (<<17), M>>4=8 (<<24)
#define GEMM_IDESC 0x8400010u

#if HAS_TCGEN05
// ---------------- tcgen05 / mbarrier helpers ----------------
__device__ __forceinline__ uint32_t elect_one() {
    uint32_t pred;
    asm volatile(
        "{\n\t.reg .pred p;\n\t"
        "elect.sync _|p, 0xFFFFFFFF;\n\t"
        "selp.b32 %0, 1, 0, p;\n\t}"
        : "=r"(pred));
    return pred;
}

#define MBARRIER_INIT(addr, cnt) \
    asm volatile("mbarrier.init.shared.b64 [%0], %1;" :: "r"(addr), "r"(cnt) : "memory")

#define MBARRIER_WAIT_PARITY(mbar_addr, phase_parity) do {                         \
    uint32_t _mbar = (uint32_t)(mbar_addr);                                        \
    uint32_t _parity = (uint32_t)(phase_parity);                                   \
    uint32_t _done;                                                                \
    asm volatile(                                                                  \
        "{\n\t.reg .pred p;\n\t"                                                   \
        "mbarrier.try_wait.parity.acquire.cta.shared::cta.b64 p, [%1], %2;\n\t"    \
        "selp.b32 %0, 1, 0, p;\n\t}"                                               \
        : "=r"(_done) : "r"(_mbar), "r"(_parity) : "memory");                      \
    if (!_done) {                                                                  \
        asm volatile(                                                              \
            "{\n\t.reg .pred P1;\n\t"                                              \
            "WAIT_LOOP_%=:\n\t"                                                    \
            "mbarrier.try_wait.parity.acquire.cta.shared::cta.b64 P1, [%0], %1, 0x989680;\n\t" \
            "@P1 bra.uni WAIT_DONE_%=;\n\t"                                        \
            "bra.uni WAIT_LOOP_%=;\n\t"                                            \
            "WAIT_DONE_%=:\n\t}"                                                   \
            :: "r"(_mbar), "r"(_parity) : "memory");                               \
    }                                                                              \
} while (0)

#define CPASYNC_MBAR_ARRIVE_NOINC(addr) \
    asm volatile("cp.async.mbarrier.arrive.noinc.shared.b64 [%0];" :: "r"(addr) : "memory")

#define FENCE_PROXY_ASYNC() \
    asm volatile("fence.proxy.async.shared::cta;" ::: "memory")

#define TCGEN05_ALLOC(smem_addr, nCols) \
    asm volatile("tcgen05.alloc.cta_group::1.sync.aligned.shared::cta.b32 [%0], %1;" \
                 :: "r"((uint32_t)(smem_addr)), "r"((uint32_t)(nCols)) : "memory")
#define TCGEN05_DEALLOC(tmem_addr, nCols) \
    asm volatile("tcgen05.dealloc.cta_group::1.sync.aligned.b32 %0, %1;" \
                 :: "r"(tmem_addr), "r"((uint32_t)(nCols)))
#define TCGEN05_RELINQUISH() \
    asm volatile("tcgen05.relinquish_alloc_permit.cta_group::1.sync.aligned;")
#define TCGEN05_COMMIT(mbar_addr) \
    asm volatile("tcgen05.commit.cta_group::1.mbarrier::arrive::one.shared::cluster.b64 [%0];" \
                 :: "r"((uint32_t)(mbar_addr)) : "memory")
#define TCGEN05_WAIT_LD() \
    asm volatile("tcgen05.wait::ld.sync.aligned;" ::: "memory")
#define TCGEN05_FENCE_BEFORE() \
    asm volatile("tcgen05.fence::before_thread_sync;" ::: "memory")
#define TCGEN05_FENCE_AFTER() \
    asm volatile("tcgen05.fence::after_thread_sync;" ::: "memory")

#define TCGEN05_LD_32X32B_X32(r, tmem_addr) \
    asm volatile( \
        "tcgen05.ld.sync.aligned.32x32b.x32.b32 " \
        "{%0, %1, %2, %3, %4, %5, %6, %7, " \
        " %8, %9, %10, %11, %12, %13, %14, %15, " \
        " %16, %17, %18, %19, %20, %21, %22, %23, " \
        " %24, %25, %26, %27, %28, %29, %30, %31}, [%32];" \
        : "=r"((r)[0]),  "=r"((r)[1]),  "=r"((r)[2]),  "=r"((r)[3]), \
          "=r"((r)[4]),  "=r"((r)[5]),  "=r"((r)[6]),  "=r"((r)[7]), \
          "=r"((r)[8]),  "=r"((r)[9]),  "=r"((r)[10]), "=r"((r)[11]), \
          "=r"((r)[12]), "=r"((r)[13]), "=r"((r)[14]), "=r"((r)[15]), \
          "=r"((r)[16]), "=r"((r)[17]), "=r"((r)[18]), "=r"((r)[19]), \
          "=r"((r)[20]), "=r"((r)[21]), "=r"((r)[22]), "=r"((r)[23]), \
          "=r"((r)[24]), "=r"((r)[25]), "=r"((r)[26]), "=r"((r)[27]), \
          "=r"((r)[28]), "=r"((r)[29]), "=r"((r)[30]), "=r"((r)[31]) \
        : "r"(tmem_addr))

static __device__ __forceinline__ uint64_t make_smem_desc(uint32_t addr) {
    const uint64_t base =
        (uint64_t(2) << 61) | (uint64_t(1) << 46) | (uint64_t(64) << 32) | (uint64_t(1) << 16);
    return base | ((uint64_t)(addr >> 4) & 0x3FFF);
}

__device__ __forceinline__ void mma_f8_ss(uint32_t d_tmem, uint64_t a_desc, uint64_t b_desc,
                                          uint32_t idesc, bool acc) {
    uint32_t en = acc ? 1u : 0u;
    asm volatile(
        "{\n\t.reg .pred p;\n\t"
        "setp.ne.u32 p, %5, 0;\n\t"
        "tcgen05.mma.cta_group::1.kind::f8f6f4 [%0], %1, %2, %3, {%4, %4, %4, %4}, p;\n\t}"
        :: "r"(d_tmem), "l"(a_desc), "l"(b_desc), "r"(idesc), "r"(0u), "r"(en)
        : "memory");
}
#endif  // HAS_TCGEN05

// ======================= gemm_tc: warp-specialized fp8 path =======================
__global__ void __launch_bounds__(TC_THREADS)
gemm_tc(float* __restrict__ out) {
#if HAS_TCGEN05
    extern __shared__ char smem[];
    uint32_t smem_base = smem_u32(smem);
    const int tid = threadIdx.x;
    const int wid = tid >> 5;              // 0 = MMA warp, 1..8 producers
    const int lid = tid & 31;
    const int m0 = blockIdx.y * BM;
    const int n0 = blockIdx.x * BN;

    // producer copy mapping (ptid 0..255): row-group rbase, 16B seg
    const int ptid  = tid - 32;
    const int rbase = ptid >> 3;
    const int seg   = ptid & 7;
    const uint8_t* gA = g_xq + (size_t)(m0 + rbase) * K_DIM + seg * 16;
    const uint8_t* gB = g_wq + (size_t)(n0 + rbase) * K_DIM + seg * 16;

    if (wid >= 1) ((float*)(smem + SM_SCALE))[ptid] = g_scale[n0 + ptid];

    if (wid == 0) TCGEN05_ALLOC(smem_base + SM_TMEM, 512);
    if (tid == 0) {
#pragma unroll
        for (int i = 0; i < N_STAGES; i++) {
            MBARRIER_INIT(smem_base + SM_FULL + i * 8, 256);  // one arrive per producer
            MBARRIER_INIT(smem_base + SM_DONE + i * 8, 1);    // tcgen05.commit
        }
    }
    __syncthreads();
    uint32_t tmem_base;
    asm volatile("ld.shared.b32 %0, [%1];" : "=r"(tmem_base) : "r"(smem_base + SM_TMEM));
    if (wid == 0) TCGEN05_RELINQUISH();

    const uint32_t tiles = smem_base + SM_TILES;

    if (wid >= 1) {
        // ---------------- producers ----------------
        int pd[N_STAGES] = {0, 0, 0};
        for (int c = 0; c < N_CHUNKS; c++) {
            const int s = c % 3;
            if (c >= 3) {                  // recycle stage s: chunk c-3's MMAs must be done
                MBARRIER_WAIT_PARITY(smem_base + SM_DONE + s * 8, pd[s]);
                pd[s] ^= 1;
            }
            const uint32_t At = tiles + s * STAGE_BYTES;
            const uint32_t Bt = At + A_TILE_BYTES;
            const int kb = c * BK;
#pragma unroll
            for (int i = 0; i < 8; i++) {
                uint32_t sw = SMEM_SWIZZLE_128B((uint32_t)((i * 32 + rbase) * 128 + seg * 16));
                const void* srcA = (const void*)(gA + (size_t)i * 32 * K_DIM + kb);
                const void* srcB = (const void*)(gB + (size_t)i * 32 * K_DIM + kb);
                asm volatile("cp.async.cg.shared.global [%0], [%1], 16;"
                             :: "r"(At + sw), "l"(srcA) : "memory");
                asm volatile("cp.async.cg.shared.global [%0], [%1], 16;"
                             :: "r"(Bt + sw), "l"(srcB) : "memory");
            }
            CPASYNC_MBAR_ARRIVE_NOINC(smem_base + SM_FULL + s * 8);
        }
        // drain: last commit goes to done[31%3=1]; its completion index is 10 -> parity 0
        MBARRIER_WAIT_PARITY(smem_base + SM_DONE + 8, 0);
    } else {
        // ---------------- MMA warp (elected lane) ----------------
        if (elect_one()) {
            int pf[N_STAGES] = {0, 0, 0};
            for (int c = 0; c < N_CHUNKS; c++) {
                const int s = c % 3;
                MBARRIER_WAIT_PARITY(smem_base + SM_FULL + s * 8, pf[s]);
                pf[s] ^= 1;
                FENCE_PROXY_ASYNC();
                const uint32_t sb = tiles + s * STAGE_BYTES;
                uint64_t ad0 = make_smem_desc(sb);            // A rows 0-127
                uint64_t ad1 = ad0 + 1024;                    // A rows 128-255 (+16KB)
                uint64_t bd  = make_smem_desc(sb + A_TILE_BYTES);
#pragma unroll
                for (int ks = 0; ks < 4; ks++) {              // 4 x K=32 = BK=128
                    const bool acc = (c > 0) || (ks > 0);
                    mma_f8_ss(tmem_base,       ad0 + ks * 2, bd + ks * 2, GEMM_IDESC, acc);
                    mma_f8_ss(tmem_base + 256, ad1 + ks * 2, bd + ks * 2, GEMM_IDESC, acc);
                }
                TCGEN05_COMMIT(smem_base + SM_DONE + s * 8);
            }
        }
    }

    __syncthreads();        // producers passed final done-wait => all MMAs complete
    TCGEN05_FENCE_AFTER();

    // epilogue: warps 1-8. TMEM subpartition = wid&3 (hw: warp%4), half = (wid-1)>>2
    if (wid >= 1) {
        const int half = (wid - 1) >> 2;
        const int sub  = wid & 3;
        const int row = m0 + half * 128 + sub * 32 + lid;
        const uint32_t dbase = tmem_base + half * 256;
        float* orow = out + (size_t)row * N_DIM + n0;
        const float* ss = (const float*)(smem + SM_SCALE);
#pragma unroll
        for (int c0 = 0; c0 < 256; c0 += 32) {
            uint32_t dr[32];
            TCGEN05_LD_32X32B_X32(dr, dbase + c0);
            TCGEN05_WAIT_LD();
#pragma unroll
            for (int j = 0; j < 32; j += 4) {
                float4 v;
                v.x = __uint_as_float(dr[j + 0]) * ss[c0 + j + 0];
                v.y = __uint_as_float(dr[j + 1]) * ss[c0 + j + 1];
                v.z = __uint_as_float(dr[j + 2]) * ss[c0 + j + 2];
                v.w = __uint_as_float(dr[j + 3]) * ss[c0 + j + 3];
                *(float4*)(orow + c0 + j) = v;
            }
        }
        TCGEN05_FENCE_BEFORE();
    }
    __syncthreads();
    if (wid == 0) TCGEN05_DEALLOC(tmem_base, 512);
#else
    (void)out;   // stub in non-'a' pass
#endif
}

// ======================= gemm_fb: insurance path (slow, correct) =======================
__global__ void __launch_bounds__(256)
gemm_fb(float* __restrict__ out) {
#if !HAS_TCGEN05
    __shared__ uint8_t As[64][64];
    __shared__ uint8_t Bs[64][64];
    const int tid = threadIdx.x;
    const int tx = tid & 15, ty = tid >> 4;
    const int n0 = blockIdx.x * 64, m0 = blockIdx.y * 64;
    const int lrow = tid >> 2;
    const int lcol = (tid & 3) * 16;

    float acc[4][4];
#pragma unroll
    for (int i = 0; i < 4; i++)
#pragma unroll
        for (int j = 0; j < 4; j++) acc[i][j] = 0.f;

    for (int kb = 0; kb < K_DIM; kb += 64) {
        *(uint4*)&As[lrow][lcol] =
            *(const uint4*)(g_xq + (size_t)(m0 + lrow) * K_DIM + kb + lcol);
        *(uint4*)&Bs[lrow][lcol] =
            *(const uint4*)(g_wq + (size_t)(n0 + lrow) * K_DIM + kb + lcol);
        __syncthreads();
#pragma unroll 8
        for (int k = 0; k < 64; k++) {
            float a[4], b[4];
#pragma unroll
            for (int i = 0; i < 4; i++) a[i] = (As[ty * 4 + i][k] & 0x80) ? -1.f : 1.f;
#pragma unroll
            for (int j = 0; j < 4; j++) b[j] = (Bs[tx * 4 + j][k] & 0x80) ? -1.f : 1.f;
#pragma unroll
            for (int i = 0; i < 4; i++)
#pragma unroll
                for (int j = 0; j < 4; j++) acc[i][j] += a[i] * b[j];
        }
        __syncthreads();
    }
#pragma unroll
    for (int i = 0; i < 4; i++)
#pragma unroll
        for (int j = 0; j < 4; j++) {
            const int col = n0 + tx * 4 + j;
            out[(size_t)(m0 + ty * 4 + i) * N_DIM + col] = acc[i][j] * g_scale[col];
        }
#else
    (void)out;   // stub in 'a' pass
#endif
}

// ---------------- launch ----------------
extern "C" void kernel_launch(void* const* d_in, const int* in_sizes, int n_in,
                              void* d_out, int out_size) {
    (void)in_sizes; (void)n_in; (void)out_size;
    const float* x = (const float*)d_in[0];
    const float* w = (const float*)d_in[1];
    float* out = (float*)d_out;

    quant_x_kernel<<<(int)((M_DIM * (size_t)K_DIM / 8) / 256), 256>>>(x);
    quant_w_fused_kernel<<<N_DIM, 256>>>(w);

    // Launch only the kernel whose body is real in the loaded cubin.
    cudaFuncAttributes fa_tc{};
    cudaFuncGetAttributes(&fa_tc, gemm_tc);

    if (fa_tc.numRegs > 24) {
        cudaFuncSetAttribute(gemm_tc, cudaFuncAttributeMaxDynamicSharedMemorySize,
                             GEMM_SMEM_REQ);
        dim3 grid_tc(N_DIM / BN, M_DIM / BM);   // (16, 32)
        gemm_tc<<<grid_tc, TC_THREADS, GEMM_SMEM_REQ>>>(out);
    } else {
        dim3 grid_fb(N_DIM / 64, M_DIM / 64);   // (64, 128)
        gemm_fb<<<grid_fb, 256>>>(out);
    }
}